// round 7
// baseline (speedup 1.0000x reference)
#include <cuda_runtime.h>
#include <cuda_bf16.h>
#include <math.h>
#include <stdint.h>

// ---------------- problem constants ----------------
#define NN0 100000
#define NN1 20000
#define NN2 4000
#define RR 3
#define EE0 160000
#define EE1 64000
#define HID 128
#define FEAT 256      // F_IN = HID + TSS + RS
#define CDIV(a,b) (((a)+(b)-1)/(b))

// ---------------- device scratch (static; no runtime alloc) ----------------
__device__ float g_feat0[(size_t)NN0 * FEAT];          // [N0,256]
__device__ float g_agg[(size_t)RR * NN1 * 768];        // [R,n_dst,768] (mx|mean|sum)
__device__ float g_scratch[(size_t)RR * NN1 * FEAT];   // fc1/fc2 concat buffer
__device__ float g_z[(size_t)RR * NN1 * HID];          // z per relation
__device__ float g_feat1[(size_t)NN1 * FEAT];          // [N1,256]
__device__ float g_wsum[RR];                           // attention score sums
__device__ int   g_cnt[RR * NN1];                      // histogram (left zeroed each replay)
__device__ int   g_cur[RR * NN1];                      // scatter cursor
__device__ int   g_rowp[RR * NN1 + 1];                 // CSR row pointers
__device__ int   g_csr[RR * EE0];                      // CSR src ids

// split-bf16 weights, transposed to [n=128][K] layout
#define W_TOTAL 1015808
__device__ __align__(16) __nv_bfloat16 g_whi[W_TOTAL];
__device__ __align__(16) __nv_bfloat16 g_wlo[W_TOTAL];

#define OFF_EMBED  0
#define OFF_L1FC1  16384
#define OFF_L1FC2  114688
#define OFF_L1FC3  409600
#define OFF_L2FC1  507904
#define OFF_L2FC2  606208
#define OFF_L2FC3  901120
#define OFF_ATTN   999424

// GEMM smem geometry
#define SLD 40                     // padded row stride (bf16 elems)
#define SL  (128 * SLD)            // one matrix slab: 5120 elems
#define GEMM_SMEM_BYTES (2 * 4 * SL * 2)   // 2 buf x (Ahi,Alo,Bhi,Blo) x bytes = 81920

// ---------------- small helpers ----------------
__device__ __forceinline__ float4 f4add(float4 a, float4 b){
    return make_float4(a.x+b.x, a.y+b.y, a.z+b.z, a.w+b.w);
}
__device__ __forceinline__ float4 f4max(float4 a, float4 b){
    return make_float4(fmaxf(a.x,b.x), fmaxf(a.y,b.y), fmaxf(a.z,b.z), fmaxf(a.w,b.w));
}
__device__ __forceinline__ float4 f4scale(float4 a, float s){
    return make_float4(a.x*s, a.y*s, a.z*s, a.w*s);
}

#define MMA_BF16(D, A, B0, B1) \
  asm volatile("mma.sync.aligned.m16n8k16.row.col.f32.bf16.bf16.f32 " \
    "{%0,%1,%2,%3}, {%4,%5,%6,%7}, {%8,%9}, {%0,%1,%2,%3};\n" \
    : "+f"((D)[0]), "+f"((D)[1]), "+f"((D)[2]), "+f"((D)[3]) \
    : "r"((A)[0]), "r"((A)[1]), "r"((A)[2]), "r"((A)[3]), "r"(B0), "r"(B1))

#define LDSM_X4(R0,R1,R2,R3, ADDR) \
  asm volatile("ldmatrix.sync.aligned.m8n8.x4.shared.b16 {%0,%1,%2,%3},[%4];" \
    : "=r"(R0), "=r"(R1), "=r"(R2), "=r"(R3) : "r"(ADDR))

__device__ __forceinline__ uint32_t smem_u32(const void* p){
    return (uint32_t)__cvta_generic_to_shared(p);
}

// ---------------- fused weight transpose+split ----------------
struct WJob { const float* src; long doff; int K; int pad; };
struct WJobs { WJob j[20]; };

__global__ void split_all(WJobs jobs, __nv_bfloat16* __restrict__ Whi,
                          __nv_bfloat16* __restrict__ Wlo)
{
    WJob jb = jobs.j[blockIdx.z];
    int K = jb.K;
    int k0 = blockIdx.x * 32;
    if (k0 >= K) return;
    int n0 = blockIdx.y * 32;
    const float* W = jb.src;
    __nv_bfloat16* whi = Whi + jb.doff;
    __nv_bfloat16* wlo = Wlo + jb.doff;

    __shared__ float sm[32][33];
    int tx = threadIdx.x, ty = threadIdx.y;
    #pragma unroll
    for (int i = 0; i < 4; i++)
        sm[ty + i * 8][tx] = W[(long)(k0 + ty + i * 8) * 128 + n0 + tx];
    __syncthreads();
    #pragma unroll
    for (int i = 0; i < 4; i++) {
        float x = sm[tx][ty + i * 8];
        __nv_bfloat16 h = __float2bfloat16(x);
        float r = x - __bfloat162float(h);
        int n = n0 + ty + i * 8;
        whi[(long)n * K + k0 + tx] = h;
        wlo[(long)n * K + k0 + tx] = __float2bfloat16(r);
    }
}

// ================= pipelined tensor-core GEMM =================
// C[M,128] = act(A[M,K] @ W[K,128] + bias). W pre-split [n=128][K].
// Double-buffered smem, one sync per 32-K slab.
// ACT: 0=none 1=relu

struct GemmCtx {
    const float* A; const __nv_bfloat16* Bhi; const __nv_bfloat16* Blo;
    int M, K, bm, lrow, lcol;
};

// load one slab's worth into registers
__device__ __forceinline__ void gemm_load_regs(const GemmCtx& c, int s,
                                               float4 va[4], uint4 vb[4])
{
    long ko = (long)s * 32 + c.lcol;
    int gr = c.bm + c.lrow;
    if (gr < c.M) {
        const float4* p = (const float4*)(c.A + (long)gr * c.K + ko);
        va[0] = p[0]; va[1] = p[1]; va[2] = p[2]; va[3] = p[3];
    } else {
        va[0] = va[1] = va[2] = va[3] = make_float4(0.f, 0.f, 0.f, 0.f);
    }
    const uint4* ph = (const uint4*)(c.Bhi + (long)c.lrow * c.K + ko);
    const uint4* pl = (const uint4*)(c.Blo + (long)c.lrow * c.K + ko);
    vb[0] = ph[0]; vb[1] = ph[1]; vb[2] = pl[0]; vb[3] = pl[1];
}

// convert + store one slab into smem buffer b
__device__ __forceinline__ void gemm_store_smem(__nv_bfloat16* sm, int b,
                                                const GemmCtx& c,
                                                const float4 va[4], const uint4 vb[4])
{
    __nv_bfloat16* base = sm + b * 4 * SL;
    __nv_bfloat16* Ahi = base;
    __nv_bfloat16* Alo = base + SL;
    __nv_bfloat16* Bh  = base + 2 * SL;
    __nv_bfloat16* Bl  = base + 3 * SL;
    uint32_t hi[8], lo[8];
    #pragma unroll
    for (int i = 0; i < 4; i++) {
        float x0 = va[i].x, x1 = va[i].y, x2 = va[i].z, x3 = va[i].w;
        __nv_bfloat162 h01 = __floats2bfloat162_rn(x0, x1);
        __nv_bfloat162 h23 = __floats2bfloat162_rn(x2, x3);
        __nv_bfloat162 l01 = __floats2bfloat162_rn(x0 - __low2float(h01),
                                                   x1 - __high2float(h01));
        __nv_bfloat162 l23 = __floats2bfloat162_rn(x2 - __low2float(h23),
                                                   x3 - __high2float(h23));
        hi[2*i]   = *(uint32_t*)&h01;  hi[2*i+1] = *(uint32_t*)&h23;
        lo[2*i]   = *(uint32_t*)&l01;  lo[2*i+1] = *(uint32_t*)&l23;
    }
    int off = c.lrow * SLD + c.lcol;
    *(uint4*)&Ahi[off]     = make_uint4(hi[0], hi[1], hi[2], hi[3]);
    *(uint4*)&Ahi[off + 8] = make_uint4(hi[4], hi[5], hi[6], hi[7]);
    *(uint4*)&Alo[off]     = make_uint4(lo[0], lo[1], lo[2], lo[3]);
    *(uint4*)&Alo[off + 8] = make_uint4(lo[4], lo[5], lo[6], lo[7]);
    *(uint4*)&Bh[off]      = vb[0];
    *(uint4*)&Bh[off + 8]  = vb[1];
    *(uint4*)&Bl[off]      = vb[2];
    *(uint4*)&Bl[off + 8]  = vb[3];
}

// MMA over one smem slab buffer
__device__ __forceinline__ void gemm_mma_slab(const __nv_bfloat16* sm, int b,
                                              int wm, int wn, int lm_r, int lm_c,
                                              float d[2][8][4])
{
    const __nv_bfloat16* base = sm + b * 4 * SL;
    const __nv_bfloat16* Ahi = base;
    const __nv_bfloat16* Alo = base + SL;
    const __nv_bfloat16* Bh  = base + 2 * SL;
    const __nv_bfloat16* Bl  = base + 3 * SL;
    #pragma unroll
    for (int ks = 0; ks < 32; ks += 16) {
        const int cc = ks + lm_c;
        uint32_t ah[2][4], al[2][4];
        #pragma unroll
        for (int fm = 0; fm < 2; fm++) {
            int r = wm * 32 + fm * 16 + lm_r;
            LDSM_X4(ah[fm][0], ah[fm][1], ah[fm][2], ah[fm][3],
                    smem_u32(&Ahi[r * SLD + cc]));
            LDSM_X4(al[fm][0], al[fm][1], al[fm][2], al[fm][3],
                    smem_u32(&Alo[r * SLD + cc]));
        }
        #pragma unroll
        for (int t = 0; t < 4; t++) {
            int nb = wn * 64 + t * 16 + lm_r;
            uint32_t bh0, bh1, bh2, bh3, bl0, bl1, bl2, bl3;
            LDSM_X4(bh0, bh1, bh2, bh3, smem_u32(&Bh[nb * SLD + cc]));
            LDSM_X4(bl0, bl1, bl2, bl3, smem_u32(&Bl[nb * SLD + cc]));
            #pragma unroll
            for (int fm = 0; fm < 2; fm++) {
                MMA_BF16(d[fm][2*t],   ah[fm], bh0, bh2);
                MMA_BF16(d[fm][2*t],   ah[fm], bl0, bl2);
                MMA_BF16(d[fm][2*t],   al[fm], bh0, bh2);
                MMA_BF16(d[fm][2*t+1], ah[fm], bh1, bh3);
                MMA_BF16(d[fm][2*t+1], ah[fm], bl1, bl3);
                MMA_BF16(d[fm][2*t+1], al[fm], bh1, bh3);
            }
        }
    }
}

template<int ACT>
__global__ __launch_bounds__(256, 2)
void tc_gemm(const float* __restrict__ A, const __nv_bfloat16* __restrict__ Bhi,
             const __nv_bfloat16* __restrict__ Blo, const float* __restrict__ bias,
             float* __restrict__ C, int M, int K, int ldc, int coff,
             long sA, long sW, long sBias, long sC)
{
    extern __shared__ __nv_bfloat16 smd[];
    GemmCtx c;
    c.A   = A   + (long)blockIdx.z * sA;
    c.Bhi = Bhi + (long)blockIdx.z * sW;
    c.Blo = Blo + (long)blockIdx.z * sW;
    bias += (long)blockIdx.z * sBias;
    C    += (long)blockIdx.z * sC;
    c.M = M; c.K = K;
    c.bm = blockIdx.x * 128;

    const int tid  = threadIdx.x;
    const int lane = tid & 31;
    const int w    = tid >> 5;
    const int wm   = w & 3;
    const int wn   = w >> 2;
    const int g    = lane >> 2;
    const int tg   = lane & 3;
    const int lm_r = lane & 15;
    const int lm_c = (lane >> 4) << 3;
    c.lrow = tid >> 1;
    c.lcol = (tid & 1) * 16;

    float d[2][8][4];
    #pragma unroll
    for (int i = 0; i < 2; i++)
        #pragma unroll
        for (int j = 0; j < 8; j++)
            #pragma unroll
            for (int q = 0; q < 4; q++) d[i][j][q] = 0.f;

    const int nsl = K >> 5;
    float4 va[4]; uint4 vb[4];

    gemm_load_regs(c, 0, va, vb);
    gemm_store_smem(smd, 0, c, va, vb);
    __syncthreads();

    for (int s = 0; s < nsl; s++) {
        bool more = (s + 1 < nsl);
        if (more) gemm_load_regs(c, s + 1, va, vb);
        gemm_mma_slab(smd, s & 1, wm, wn, lm_r, lm_c, d);
        if (more) {
            gemm_store_smem(smd, (s + 1) & 1, c, va, vb);
            __syncthreads();
        }
    }

    // epilogue
    #pragma unroll
    for (int fn = 0; fn < 8; fn++) {
        int ncol = wn * 64 + fn * 8 + 2 * tg;
        float2 bb = *(const float2*)&bias[ncol];
        int col = coff + ncol;
        #pragma unroll
        for (int fm = 0; fm < 2; fm++) {
            int r0 = c.bm + wm * 32 + fm * 16 + g;
            float v0 = d[fm][fn][0] + bb.x;
            float v1 = d[fm][fn][1] + bb.y;
            float v2 = d[fm][fn][2] + bb.x;
            float v3 = d[fm][fn][3] + bb.y;
            if (ACT == 1) {
                v0 = fmaxf(v0, 0.f); v1 = fmaxf(v1, 0.f);
                v2 = fmaxf(v2, 0.f); v3 = fmaxf(v3, 0.f);
            }
            if (r0 < M)     *(float2*)&C[(long)r0 * ldc + col]       = make_float2(v0, v1);
            if (r0 + 8 < M) *(float2*)&C[(long)(r0 + 8) * ldc + col] = make_float2(v2, v3);
        }
    }
}

// attention GEMM: tanh(z@W1+b1) dotted with w2, reduced straight into g_wsum[r].
// No C output. M = RR*relN.
__global__ __launch_bounds__(256, 2)
void tc_gemm_attn(const float* __restrict__ A, const __nv_bfloat16* __restrict__ Bhi,
                  const __nv_bfloat16* __restrict__ Blo, const float* __restrict__ bias,
                  const float* __restrict__ w2, int relN)
{
    extern __shared__ __nv_bfloat16 smd[];
    __shared__ float red[RR];
    GemmCtx c;
    c.A = A; c.Bhi = Bhi; c.Blo = Blo;
    c.M = RR * relN; c.K = HID;
    c.bm = blockIdx.x * 128;

    const int tid  = threadIdx.x;
    const int lane = tid & 31;
    const int w    = tid >> 5;
    const int wm   = w & 3;
    const int wn   = w >> 2;
    const int g    = lane >> 2;
    const int tg   = lane & 3;
    const int lm_r = lane & 15;
    const int lm_c = (lane >> 4) << 3;
    c.lrow = tid >> 1;
    c.lcol = (tid & 1) * 16;

    if (tid < RR) red[tid] = 0.f;

    float d[2][8][4];
    #pragma unroll
    for (int i = 0; i < 2; i++)
        #pragma unroll
        for (int j = 0; j < 8; j++)
            #pragma unroll
            for (int q = 0; q < 4; q++) d[i][j][q] = 0.f;

    const int nsl = HID >> 5;   // 4
    float4 va[4]; uint4 vb[4];

    gemm_load_regs(c, 0, va, vb);
    gemm_store_smem(smd, 0, c, va, vb);
    __syncthreads();

    for (int s = 0; s < nsl; s++) {
        bool more = (s + 1 < nsl);
        if (more) gemm_load_regs(c, s + 1, va, vb);
        gemm_mma_slab(smd, s & 1, wm, wn, lm_r, lm_c, d);
        if (more) {
            gemm_store_smem(smd, (s + 1) & 1, c, va, vb);
        }
        __syncthreads();   // last sync also protects red[] init
    }

    float part[RR] = {0.f, 0.f, 0.f};
    #pragma unroll
    for (int fn = 0; fn < 8; fn++) {
        int ncol = wn * 64 + fn * 8 + 2 * tg;
        float2 bb = *(const float2*)&bias[ncol];
        float2 ww = *(const float2*)&w2[ncol];
        #pragma unroll
        for (int fm = 0; fm < 2; fm++) {
            int r0 = c.bm + wm * 32 + fm * 16 + g;
            int r1 = r0 + 8;
            if (r0 < c.M) {
                float s0 = tanhf(d[fm][fn][0] + bb.x) * ww.x
                         + tanhf(d[fm][fn][1] + bb.y) * ww.y;
                int rel = r0 / relN;
                part[0] += (rel == 0) ? s0 : 0.f;
                part[1] += (rel == 1) ? s0 : 0.f;
                part[2] += (rel == 2) ? s0 : 0.f;
            }
            if (r1 < c.M) {
                float s1 = tanhf(d[fm][fn][2] + bb.x) * ww.x
                         + tanhf(d[fm][fn][3] + bb.y) * ww.y;
                int rel = r1 / relN;
                part[0] += (rel == 0) ? s1 : 0.f;
                part[1] += (rel == 1) ? s1 : 0.f;
                part[2] += (rel == 2) ? s1 : 0.f;
            }
        }
    }
    #pragma unroll
    for (int r = 0; r < RR; r++) {
        // warp reduce then shared atomic
        float v = part[r];
        for (int off = 16; off > 0; off >>= 1) v += __shfl_down_sync(0xffffffffu, v, off);
        if (lane == 0 && v != 0.f) atomicAdd(&red[r], v);
    }
    __syncthreads();
    if (tid < RR) atomicAdd(&g_wsum[tid], red[tid]);
}

// ---------------- gather tss/rs embeds into feature cols [128,256) ----------------
__global__ void gather_embed(const float* __restrict__ tss, const float* __restrict__ rs,
                             const int* __restrict__ nid, float* __restrict__ feat, int n)
{
    int gw   = (blockIdx.x * blockDim.x + threadIdx.x) >> 5;
    int lane = threadIdx.x & 31;
    if (gw >= n) return;
    int id = nid[gw];
    float4* out = (float4*)(feat + (long)gw * FEAT);
    if (lane < 16) {
        out[32 + lane] = ((const float4*)(tss + (long)id * 64))[lane];
    } else {
        out[48 + (lane - 16)] = ((const float4*)(rs + (long)id * 64))[lane - 16];
    }
}

// ---------------- CSR build ----------------
__global__ void hist_kernel(const int* __restrict__ dst, int total, int E, int ndst)
{
    int i = blockIdx.x * blockDim.x + threadIdx.x;
    if (i >= total) return;
    int r = i / E;
    atomicAdd(&g_cnt[r * ndst + dst[i]], 1);
}

// exclusive scan of g_cnt -> g_rowp + cursor copy; zero g_cnt and g_wsum
__global__ void scan_kernel(int n)
{
    __shared__ int ssum[1024];
    int tid   = threadIdx.x;
    int chunk = (n + 1023) >> 10;
    int base  = tid * chunk;
    int end   = min(base + chunk, n);

    int s = 0;
    for (int i = base; i < end; i++) s += g_cnt[i];
    ssum[tid] = s;
    __syncthreads();

    for (int off = 1; off < 1024; off <<= 1) {
        int v = (tid >= off) ? ssum[tid - off] : 0;
        __syncthreads();
        ssum[tid] += v;
        __syncthreads();
    }

    int p = ssum[tid] - s;
    for (int i = base; i < end; i++) {
        g_rowp[i] = p; g_cur[i] = p;
        p += g_cnt[i];
    }
    if (tid == 1023) g_rowp[n] = ssum[1023];
    if (tid < RR) g_wsum[tid] = 0.f;
    __syncthreads();
    for (int i = tid; i < n; i += 1024) g_cnt[i] = 0;
}

__global__ void scatter_kernel(const int* __restrict__ src, const int* __restrict__ dst,
                               int total, int E, int ndst)
{
    int i = blockIdx.x * blockDim.x + threadIdx.x;
    if (i >= total) return;
    int r   = i / E;
    int pos = atomicAdd(&g_cur[r * ndst + dst[i]], 1);
    g_csr[pos] = src[i];
}

// ---------------- warp-per-dst aggregation ----------------
__global__ void aggregate_kernel(const float* __restrict__ feat, float* __restrict__ agg, int total)
{
    int gw   = (blockIdx.x * blockDim.x + threadIdx.x) >> 5;
    int lane = threadIdx.x & 31;
    if (gw >= total) return;

    int s = g_rowp[gw], e = g_rowp[gw + 1];
    float4 sa = make_float4(0.f, 0.f, 0.f, 0.f), sb = sa;
    float4 ma = make_float4(-INFINITY, -INFINITY, -INFINITY, -INFINITY), mb = ma;

    int i = s;
    for (; i + 1 < e; i += 2) {
        int s0 = g_csr[i], s1 = g_csr[i + 1];
        const float4* p0 = (const float4*)(feat + (long)s0 * FEAT);
        const float4* p1 = (const float4*)(feat + (long)s1 * FEAT);
        float4 va0 = p0[lane], vb0 = p0[lane + 32];
        float4 va1 = p1[lane], vb1 = p1[lane + 32];
        sa = f4add(sa, f4add(va0, va1));  sb = f4add(sb, f4add(vb0, vb1));
        ma = f4max(ma, f4max(va0, va1));  mb = f4max(mb, f4max(vb0, vb1));
    }
    if (i < e) {
        int s0 = g_csr[i];
        const float4* p0 = (const float4*)(feat + (long)s0 * FEAT);
        float4 va0 = p0[lane], vb0 = p0[lane + 32];
        sa = f4add(sa, va0);  sb = f4add(sb, vb0);
        ma = f4max(ma, va0);  mb = f4max(mb, vb0);
    }

    float deg = (float)(e - s);
    if (e == s) { ma = make_float4(0.f,0.f,0.f,0.f); mb = ma; }
    float inv = 1.f / fmaxf(deg, 1.f);

    float4* o = (float4*)(agg + (long)gw * 768);
    o[lane]       = ma;                 o[32 + lane]  = mb;
    o[64 + lane]  = f4scale(sa, inv);   o[96 + lane]  = f4scale(sb, inv);
    o[128 + lane] = sa;                 o[160 + lane] = sb;
}

// ---------------- combine (attention mix) ----------------
__global__ void combine_kernel(const float* __restrict__ z, int N,
                               float* __restrict__ out, int ldo,
                               const float* __restrict__ tss, const float* __restrict__ rs,
                               const int* __restrict__ nid)
{
    int gw   = (blockIdx.x * blockDim.x + threadIdx.x) >> 5;
    int lane = threadIdx.x & 31;
    if (gw >= N) return;

    float w0 = g_wsum[0] / (float)N;
    float w1 = g_wsum[1] / (float)N;
    float w2 = g_wsum[2] / (float)N;
    float m  = fmaxf(w0, fmaxf(w1, w2));
    float e0 = expf(w0 - m), e1 = expf(w1 - m), e2 = expf(w2 - m);
    float inv = 1.f / (e0 + e1 + e2);
    float b0 = e0 * inv, b1 = e1 * inv, b2 = e2 * inv;

    long stride = (long)N * HID;
    const float4* z0 = (const float4*)(z + (long)gw * HID);
    const float4* z1 = (const float4*)(z + stride + (long)gw * HID);
    const float4* z2 = (const float4*)(z + 2 * stride + (long)gw * HID);
    float4 v0 = z0[lane], v1 = z1[lane], v2 = z2[lane];
    float4 h;
    h.x = fmaxf(b0 * v0.x + b1 * v1.x + b2 * v2.x, 0.f);
    h.y = fmaxf(b0 * v0.y + b1 * v1.y + b2 * v2.y, 0.f);
    h.z = fmaxf(b0 * v0.z + b1 * v1.z + b2 * v2.z, 0.f);
    h.w = fmaxf(b0 * v0.w + b1 * v1.w + b2 * v2.w, 0.f);

    float4* orow = (float4*)(out + (long)gw * ldo);
    orow[lane] = h;

    int id = nid[gw];
    if (lane < 16) orow[32 + lane] = ((const float4*)(tss + (long)id * 64))[lane];
    else           orow[48 + (lane - 16)] = ((const float4*)(rs + (long)id * 64))[lane - 16];
}

// ---------------- fused layer-2 combine + prediction ----------------
__global__ void combine_pred_kernel(const float* __restrict__ z, int N,
                                    const float* __restrict__ pw, const float* __restrict__ pb,
                                    float* __restrict__ out)
{
    int gw   = (blockIdx.x * blockDim.x + threadIdx.x) >> 5;
    int lane = threadIdx.x & 31;
    if (gw >= N) return;

    float w0 = g_wsum[0] / (float)N;
    float w1 = g_wsum[1] / (float)N;
    float w2 = g_wsum[2] / (float)N;
    float m  = fmaxf(w0, fmaxf(w1, w2));
    float e0 = expf(w0 - m), e1 = expf(w1 - m), e2 = expf(w2 - m);
    float inv = 1.f / (e0 + e1 + e2);
    float b0 = e0 * inv, b1 = e1 * inv, b2 = e2 * inv;

    long stride = (long)N * HID;
    const float4* z0 = (const float4*)(z + (long)gw * HID);
    const float4* z1 = (const float4*)(z + stride + (long)gw * HID);
    const float4* z2 = (const float4*)(z + 2 * stride + (long)gw * HID);
    float4 v0 = z0[lane], v1 = z1[lane], v2 = z2[lane];
    float4 h;
    h.x = b0 * v0.x + b1 * v1.x + b2 * v2.x;
    h.y = b0 * v0.y + b1 * v1.y + b2 * v2.y;
    h.z = b0 * v0.z + b1 * v1.z + b2 * v2.z;
    h.w = b0 * v0.w + b1 * v1.w + b2 * v2.w;

    float4 w = ((const float4*)pw)[lane];
    float s = h.x * w.x + h.y * w.y + h.z * w.z + h.w * w.w;
    for (int off = 16; off > 0; off >>= 1) s += __shfl_down_sync(0xffffffffu, s, off);
    if (lane == 0) out[gw] = 1.f / (1.f + expf(-(s + pb[0])));
}

// ---------------- host ----------------
extern "C" void kernel_launch(void* const* d_in, const int* in_sizes, int n_in,
                              void* d_out, int out_size)
{
    const float* x_user   = (const float*)d_in[0];
    const float* tss      = (const float*)d_in[1];
    const float* rs       = (const float*)d_in[2];
    const int*   src_nid0 = (const int*)  d_in[3];
    const int*   src_nid1 = (const int*)  d_in[4];
    const int*   e0_src   = (const int*)  d_in[5];
    const int*   e0_dst   = (const int*)  d_in[6];
    const int*   e1_src   = (const int*)  d_in[7];
    const int*   e1_dst   = (const int*)  d_in[8];
    const float* embed_w  = (const float*)d_in[9];
    const float* embed_b  = (const float*)d_in[10];
    const float* l1_fc1_w = (const float*)d_in[11];
    const float* l1_fc1_b = (const float*)d_in[12];
    const float* l1_fc2_w = (const float*)d_in[13];
    const float* l1_fc2_b = (const float*)d_in[14];
    const float* l1_fc3_w = (const float*)d_in[15];
    const float* l1_fc3_b = (const float*)d_in[16];
    const float* l2_fc1_w = (const float*)d_in[17];
    const float* l2_fc1_b = (const float*)d_in[18];
    const float* l2_fc2_w = (const float*)d_in[19];
    const float* l2_fc2_b = (const float*)d_in[20];
    const float* l2_fc3_w = (const float*)d_in[21];
    const float* l2_fc3_b = (const float*)d_in[22];
    const float* attn_w1  = (const float*)d_in[23];
    const float* attn_b1  = (const float*)d_in[24];
    const float* attn_w2  = (const float*)d_in[25];
    const float* pred_w   = (const float*)d_in[26];
    const float* pred_b   = (const float*)d_in[27];
    float* out = (float*)d_out;

    float *feat0, *agg, *scratch, *z, *feat1;
    __nv_bfloat16 *whi, *wlo;
    cudaGetSymbolAddress((void**)&feat0,   g_feat0);
    cudaGetSymbolAddress((void**)&agg,     g_agg);
    cudaGetSymbolAddress((void**)&scratch, g_scratch);
    cudaGetSymbolAddress((void**)&z,       g_z);
    cudaGetSymbolAddress((void**)&feat1,   g_feat1);
    cudaGetSymbolAddress((void**)&whi,     g_whi);
    cudaGetSymbolAddress((void**)&wlo,     g_wlo);

    cudaFuncSetAttribute(tc_gemm<0>, cudaFuncAttributeMaxDynamicSharedMemorySize, GEMM_SMEM_BYTES);
    cudaFuncSetAttribute(tc_gemm<1>, cudaFuncAttributeMaxDynamicSharedMemorySize, GEMM_SMEM_BYTES);
    cudaFuncSetAttribute(tc_gemm_attn, cudaFuncAttributeMaxDynamicSharedMemorySize, GEMM_SMEM_BYTES);

    // ---- fused weight split ----
    WJobs jobs;
    {
        int n = 0;
        jobs.j[n++] = {embed_w, OFF_EMBED, 128, 0};
        for (int r = 0; r < RR; r++)
            jobs.j[n++] = {l1_fc1_w + (long)r*256*128, OFF_L1FC1 + (long)r*256*128, 256, 0};
        for (int r = 0; r < RR; r++)
            jobs.j[n++] = {l1_fc2_w + (long)r*768*128, OFF_L1FC2 + (long)r*768*128, 768, 0};
        for (int r = 0; r < RR; r++)
            jobs.j[n++] = {l1_fc3_w + (long)r*256*128, OFF_L1FC3 + (long)r*256*128, 256, 0};
        for (int r = 0; r < RR; r++)
            jobs.j[n++] = {l2_fc1_w + (long)r*256*128, OFF_L2FC1 + (long)r*256*128, 256, 0};
        for (int r = 0; r < RR; r++)
            jobs.j[n++] = {l2_fc2_w + (long)r*768*128, OFF_L2FC2 + (long)r*768*128, 768, 0};
        for (int r = 0; r < RR; r++)
            jobs.j[n++] = {l2_fc3_w + (long)r*256*128, OFF_L2FC3 + (long)r*256*128, 256, 0};
        jobs.j[n++] = {attn_w1, OFF_ATTN, 128, 0};
    }
    split_all<<<dim3(24, 4, 20), dim3(32, 8)>>>(jobs, whi, wlo);

    // ---- embed + feat0 ----
    tc_gemm<0><<<dim3(CDIV(NN0,128),1,1),256,GEMM_SMEM_BYTES>>>(x_user, whi+OFF_EMBED, wlo+OFF_EMBED,
        embed_b, feat0, NN0, 128, FEAT, 0, 0,0,0,0);
    gather_embed<<<CDIV(NN0*32,256),256>>>(tss, rs, src_nid0, feat0, NN0);

    // ---- layer 1 CSR + aggregate ----
    hist_kernel<<<CDIV(RR*EE0,256),256>>>(e0_dst, RR*EE0, EE0, NN1);
    scan_kernel<<<1,1024>>>(RR*NN1);
    scatter_kernel<<<CDIV(RR*EE0,256),256>>>(e0_src, e0_dst, RR*EE0, EE0, NN1);
    aggregate_kernel<<<CDIV(RR*NN1*32,256),256>>>(feat0, agg, RR*NN1);

    // ---- layer 1 GEMMs ----
    tc_gemm<1><<<dim3(CDIV(NN1,128),1,RR),256,GEMM_SMEM_BYTES>>>(agg, whi+OFF_L1FC2, wlo+OFF_L1FC2,
        l1_fc2_b, scratch, NN1, 768, FEAT, 0, (long)NN1*768, 768*128, 128, (long)NN1*FEAT);
    tc_gemm<1><<<dim3(CDIV(NN1,128),1,RR),256,GEMM_SMEM_BYTES>>>(feat0, whi+OFF_L1FC1, wlo+OFF_L1FC1,
        l1_fc1_b, scratch, NN1, 256, FEAT, 128, 0, 256*128, 128, (long)NN1*FEAT);
    tc_gemm<0><<<dim3(CDIV(NN1,128),1,RR),256,GEMM_SMEM_BYTES>>>(scratch, whi+OFF_L1FC3, wlo+OFF_L1FC3,
        l1_fc3_b, z, NN1, 256, HID, 0, (long)NN1*FEAT, 256*128, 128, (long)NN1*HID);

    // ---- attention 1 (fused reduce) -> feat1 ----
    tc_gemm_attn<<<dim3(CDIV(RR*NN1,128),1,1),256,GEMM_SMEM_BYTES>>>(z, whi+OFF_ATTN, wlo+OFF_ATTN,
        attn_b1, attn_w2, NN1);
    combine_kernel<<<CDIV(NN1*32,256),256>>>(z, NN1, feat1, FEAT, tss, rs, src_nid1);

    // ---- layer 2 CSR + aggregate ----
    hist_kernel<<<CDIV(RR*EE1,256),256>>>(e1_dst, RR*EE1, EE1, NN2);
    scan_kernel<<<1,1024>>>(RR*NN2);
    scatter_kernel<<<CDIV(RR*EE1,256),256>>>(e1_src, e1_dst, RR*EE1, EE1, NN2);
    aggregate_kernel<<<CDIV(RR*NN2*32,256),256>>>(feat1, agg, RR*NN2);

    // ---- layer 2 GEMMs ----
    tc_gemm<1><<<dim3(CDIV(NN2,128),1,RR),256,GEMM_SMEM_BYTES>>>(agg, whi+OFF_L2FC2, wlo+OFF_L2FC2,
        l2_fc2_b, scratch, NN2, 768, FEAT, 0, (long)NN2*768, 768*128, 128, (long)NN2*FEAT);
    tc_gemm<1><<<dim3(CDIV(NN2,128),1,RR),256,GEMM_SMEM_BYTES>>>(feat1, whi+OFF_L2FC1, wlo+OFF_L2FC1,
        l2_fc1_b, scratch, NN2, 256, FEAT, 128, 0, 256*128, 128, (long)NN2*FEAT);
    tc_gemm<0><<<dim3(CDIV(NN2,128),1,RR),256,GEMM_SMEM_BYTES>>>(scratch, whi+OFF_L2FC3, wlo+OFF_L2FC3,
        l2_fc3_b, z, NN2, 256, HID, 0, (long)NN2*FEAT, 256*128, 128, (long)NN2*HID);

    // ---- attention 2 + fused combine/pred ----
    tc_gemm_attn<<<dim3(CDIV(RR*NN2,128),1,1),256,GEMM_SMEM_BYTES>>>(z, whi+OFF_ATTN, wlo+OFF_ATTN,
        attn_b1, attn_w2, NN2);
    combine_pred_kernel<<<CDIV(NN2*32,256),256>>>(z, NN2, pred_w, pred_b, out);
}

// round 8
// speedup vs baseline: 1.0647x; 1.0647x over previous
#include <cuda_runtime.h>
#include <cuda_bf16.h>
#include <math.h>
#include <stdint.h>

// ---------------- problem constants ----------------
#define NN0 100000
#define NN1 20000
#define NN2 4000
#define RR 3
#define EE0 160000
#define EE1 64000
#define HID 128
#define FEAT 256
#define CDIV(a,b) (((a)+(b)-1)/(b))

// ---------------- device scratch (static; no runtime alloc) ----------------
// split-bf16 activations (hi/lo pairs)
__device__ __align__(16) __nv_bfloat16 g_xhi[(size_t)NN0 * 128];
__device__ __align__(16) __nv_bfloat16 g_xlo[(size_t)NN0 * 128];
__device__ __align__(16) __nv_bfloat16 g_f0hi[(size_t)NN0 * FEAT];
__device__ __align__(16) __nv_bfloat16 g_f0lo[(size_t)NN0 * FEAT];
__device__ __align__(16) __nv_bfloat16 g_agghi[(size_t)RR * NN1 * 768];
__device__ __align__(16) __nv_bfloat16 g_agglo[(size_t)RR * NN1 * 768];
__device__ __align__(16) __nv_bfloat16 g_schi[(size_t)RR * NN1 * FEAT];
__device__ __align__(16) __nv_bfloat16 g_sclo[(size_t)RR * NN1 * FEAT];
__device__ __align__(16) __nv_bfloat16 g_zhi[(size_t)RR * NN1 * HID];
__device__ __align__(16) __nv_bfloat16 g_zlo[(size_t)RR * NN1 * HID];
__device__ __align__(16) __nv_bfloat16 g_f1hi[(size_t)NN1 * FEAT];
__device__ __align__(16) __nv_bfloat16 g_f1lo[(size_t)NN1 * FEAT];
__device__ float g_z[(size_t)RR * NN1 * HID];          // fp32 z for combine
__device__ float g_wsum[RR];
__device__ int   g_cnt[RR * NN1];
__device__ int   g_cur[RR * NN1];
__device__ int   g_rowp[RR * NN1 + 1];
__device__ int   g_csr[RR * EE0];

// split-bf16 weights, transposed to [n=128][K]
#define W_TOTAL 1015808
__device__ __align__(16) __nv_bfloat16 g_whi[W_TOTAL];
__device__ __align__(16) __nv_bfloat16 g_wlo[W_TOTAL];

#define OFF_EMBED  0
#define OFF_L1FC1  16384
#define OFF_L1FC2  114688
#define OFF_L1FC3  409600
#define OFF_L2FC1  507904
#define OFF_L2FC2  606208
#define OFF_L2FC3  901120
#define OFF_ATTN   999424

// GEMM smem geometry
#define SLD 40
#define SL  (128 * SLD)                    // 5120 elems per matrix slab
#define GEMM_SMEM_BYTES (2 * 4 * SL * 2)   // 81920 bytes

// ---------------- helpers ----------------
#define MMA_BF16(D, A, B0, B1) \
  asm volatile("mma.sync.aligned.m16n8k16.row.col.f32.bf16.bf16.f32 " \
    "{%0,%1,%2,%3}, {%4,%5,%6,%7}, {%8,%9}, {%0,%1,%2,%3};\n" \
    : "+f"((D)[0]), "+f"((D)[1]), "+f"((D)[2]), "+f"((D)[3]) \
    : "r"((A)[0]), "r"((A)[1]), "r"((A)[2]), "r"((A)[3]), "r"(B0), "r"(B1))

#define LDSM_X4(R0,R1,R2,R3, ADDR) \
  asm volatile("ldmatrix.sync.aligned.m8n8.x4.shared.b16 {%0,%1,%2,%3},[%4];" \
    : "=r"(R0), "=r"(R1), "=r"(R2), "=r"(R3) : "r"(ADDR))

__device__ __forceinline__ uint32_t smem_u32(const void* p){
    return (uint32_t)__cvta_generic_to_shared(p);
}
__device__ __forceinline__ void cp16(uint32_t dst, const __nv_bfloat16* src, int sz){
    asm volatile("cp.async.cg.shared.global [%0], [%1], 16, %2;\n"
                 :: "r"(dst), "l"(src), "r"(sz));
}
#define CP_COMMIT() asm volatile("cp.async.commit_group;\n")

// pack two floats into bf16x2 hi word, residual lo word
__device__ __forceinline__ uint32_t packsplit(float a, float b, uint32_t& lo){
    __nv_bfloat162 h = __floats2bfloat162_rn(a, b);
    __nv_bfloat162 l = __floats2bfloat162_rn(a - __low2float(h), b - __high2float(h));
    lo = *(uint32_t*)&l;
    return *(uint32_t*)&h;
}
__device__ __forceinline__ void split8(const float v[8], uint4& hi, uint4& lo){
    uint32_t h[4], l[4];
    #pragma unroll
    for (int i = 0; i < 4; i++) h[i] = packsplit(v[2*i], v[2*i+1], l[i]);
    hi = make_uint4(h[0], h[1], h[2], h[3]);
    lo = make_uint4(l[0], l[1], l[2], l[3]);
}
__device__ __forceinline__ void unpack8(uint4 h, uint4 l, float v[8]){
    const __nv_bfloat162* hp = (const __nv_bfloat162*)&h;
    const __nv_bfloat162* lp = (const __nv_bfloat162*)&l;
    #pragma unroll
    for (int i = 0; i < 4; i++) {
        v[2*i]   = __low2float(hp[i])  + __low2float(lp[i]);
        v[2*i+1] = __high2float(hp[i]) + __high2float(lp[i]);
    }
}

// ---------------- fused weight transpose+split ----------------
struct WJob { const float* src; long doff; int K; int pad; };
struct WJobs { WJob j[20]; };

__global__ void split_all(WJobs jobs, __nv_bfloat16* __restrict__ Whi,
                          __nv_bfloat16* __restrict__ Wlo)
{
    WJob jb = jobs.j[blockIdx.z];
    int K = jb.K;
    int k0 = blockIdx.x * 32;
    if (k0 >= K) return;
    int n0 = blockIdx.y * 32;
    const float* W = jb.src;
    __nv_bfloat16* whi = Whi + jb.doff;
    __nv_bfloat16* wlo = Wlo + jb.doff;

    __shared__ float sm[32][33];
    int tx = threadIdx.x, ty = threadIdx.y;
    #pragma unroll
    for (int i = 0; i < 4; i++)
        sm[ty + i * 8][tx] = W[(long)(k0 + ty + i * 8) * 128 + n0 + tx];
    __syncthreads();
    #pragma unroll
    for (int i = 0; i < 4; i++) {
        float x = sm[tx][ty + i * 8];
        __nv_bfloat16 h = __float2bfloat16(x);
        float r = x - __bfloat162float(h);
        int n = n0 + ty + i * 8;
        whi[(long)n * K + k0 + tx] = h;
        wlo[(long)n * K + k0 + tx] = __float2bfloat16(r);
    }
}

// ---------------- split x_user into bf16 hi/lo ----------------
__global__ void split_x(const float* __restrict__ x, __nv_bfloat16* __restrict__ xhi,
                        __nv_bfloat16* __restrict__ xlo, long n4)
{
    long i = (long)blockIdx.x * blockDim.x + threadIdx.x;
    if (i >= n4) return;
    float4 v = ((const float4*)x)[i];
    uint32_t l0, l1;
    uint32_t h0 = packsplit(v.x, v.y, l0);
    uint32_t h1 = packsplit(v.z, v.w, l1);
    ((uint2*)xhi)[i] = make_uint2(h0, h1);
    ((uint2*)xlo)[i] = make_uint2(l0, l1);
}

// ================= cp.async pipelined tensor-core GEMM =================
// C = act(A[M,K] @ W[K,128] + bias); A given split bf16 [M][K]; W split [128][K].

struct StageCtx {
    const __nv_bfloat16 *ahi, *alo, *bhi, *blo;  // row-adjusted base pointers
    uint32_t sbase;    // smem byte base
    uint32_t soff;     // per-thread byte offset within a matrix slab
    int lcol;          // 0 or 16
    int szA;           // 16 or 0 (OOB)
};

__device__ __forceinline__ void stage_slab(const StageCtx& st, int s, int b)
{
    long ko = ((long)s << 5) + st.lcol;
    uint32_t d = st.sbase + (uint32_t)(b * 4 * SL * 2) + st.soff;
    cp16(d,                  st.ahi + ko,     st.szA);
    cp16(d + 16,             st.ahi + ko + 8, st.szA);
    cp16(d + SL*2,           st.alo + ko,     st.szA);
    cp16(d + SL*2 + 16,      st.alo + ko + 8, st.szA);
    cp16(d + 2*SL*2,         st.bhi + ko,     16);
    cp16(d + 2*SL*2 + 16,    st.bhi + ko + 8, 16);
    cp16(d + 3*SL*2,         st.blo + ko,     16);
    cp16(d + 3*SL*2 + 16,    st.blo + ko + 8, 16);
    CP_COMMIT();
}

__device__ __forceinline__ void gemm_mma_slab(const __nv_bfloat16* sm, int b,
                                              int wm, int wn, int lm_r, int lm_c,
                                              float d[2][8][4])
{
    const __nv_bfloat16* base = sm + b * 4 * SL;
    const __nv_bfloat16* Ahi = base;
    const __nv_bfloat16* Alo = base + SL;
    const __nv_bfloat16* Bh  = base + 2 * SL;
    const __nv_bfloat16* Bl  = base + 3 * SL;
    #pragma unroll
    for (int ks = 0; ks < 32; ks += 16) {
        const int cc = ks + lm_c;
        uint32_t ah[2][4], al[2][4];
        #pragma unroll
        for (int fm = 0; fm < 2; fm++) {
            int r = wm * 32 + fm * 16 + lm_r;
            LDSM_X4(ah[fm][0], ah[fm][1], ah[fm][2], ah[fm][3],
                    smem_u32(&Ahi[r * SLD + cc]));
            LDSM_X4(al[fm][0], al[fm][1], al[fm][2], al[fm][3],
                    smem_u32(&Alo[r * SLD + cc]));
        }
        #pragma unroll
        for (int t = 0; t < 4; t++) {
            int nb = wn * 64 + t * 16 + lm_r;
            uint32_t bh0, bh1, bh2, bh3, bl0, bl1, bl2, bl3;
            LDSM_X4(bh0, bh1, bh2, bh3, smem_u32(&Bh[nb * SLD + cc]));
            LDSM_X4(bl0, bl1, bl2, bl3, smem_u32(&Bl[nb * SLD + cc]));
            #pragma unroll
            for (int fm = 0; fm < 2; fm++) {
                MMA_BF16(d[fm][2*t],   ah[fm], bh0, bh2);
                MMA_BF16(d[fm][2*t],   ah[fm], bl0, bl2);
                MMA_BF16(d[fm][2*t],   al[fm], bh0, bh2);
                MMA_BF16(d[fm][2*t+1], ah[fm], bh1, bh3);
                MMA_BF16(d[fm][2*t+1], ah[fm], bl1, bl3);
                MMA_BF16(d[fm][2*t+1], al[fm], bh1, bh3);
            }
        }
    }
}

// mainloop shared by both GEMM kernels
#define GEMM_MAINLOOP(NSL) \
    stage_slab(st, 0, 0); \
    for (int s = 0; s < (NSL); s++) { \
        bool more = (s + 1 < (NSL)); \
        if (more) stage_slab(st, s + 1, (s + 1) & 1); \
        if (more) asm volatile("cp.async.wait_group 1;\n"); \
        else      asm volatile("cp.async.wait_group 0;\n"); \
        __syncthreads(); \
        gemm_mma_slab(smd, s & 1, wm, wn, lm_r, lm_c, d); \
        __syncthreads(); \
    }

// ACT: 0=none 1=relu; WF32: write fp32 C; WSPLIT: write split bf16 Chi/Clo
template<int ACT, int WF32, int WSPLIT>
__global__ __launch_bounds__(256, 2)
void tc_gemm(const __nv_bfloat16* __restrict__ Ahi_, const __nv_bfloat16* __restrict__ Alo_,
             const __nv_bfloat16* __restrict__ Bhi_, const __nv_bfloat16* __restrict__ Blo_,
             const float* __restrict__ bias, float* __restrict__ Cf,
             __nv_bfloat16* __restrict__ Chi, __nv_bfloat16* __restrict__ Clo,
             int M, int K, int ldc, int coff,
             long sA, long sW, long sBias, long sC)
{
    extern __shared__ __nv_bfloat16 smd[];
    const __nv_bfloat16* Ahi = Ahi_ + (long)blockIdx.z * sA;
    const __nv_bfloat16* Alo = Alo_ + (long)blockIdx.z * sA;
    const __nv_bfloat16* Bhi = Bhi_ + (long)blockIdx.z * sW;
    const __nv_bfloat16* Blo = Blo_ + (long)blockIdx.z * sW;
    bias += (long)blockIdx.z * sBias;
    if (WF32)   Cf  += (long)blockIdx.z * sC;
    if (WSPLIT) { Chi += (long)blockIdx.z * sC; Clo += (long)blockIdx.z * sC; }

    const int bm   = blockIdx.x * 128;
    const int tid  = threadIdx.x;
    const int lane = tid & 31;
    const int w    = tid >> 5;
    const int wm   = w & 3;
    const int wn   = w >> 2;
    const int g    = lane >> 2;
    const int tg   = lane & 3;
    const int lm_r = lane & 15;
    const int lm_c = (lane >> 4) << 3;
    const int lrow = tid >> 1;
    const int lcol = (tid & 1) * 16;

    StageCtx st;
    {
        int gr = bm + lrow;
        int cr = (gr < M) ? gr : (M - 1);
        st.ahi = Ahi + (long)cr * K;
        st.alo = Alo + (long)cr * K;
        st.bhi = Bhi + (long)lrow * K;
        st.blo = Blo + (long)lrow * K;
        st.sbase = smem_u32(smd);
        st.soff  = (uint32_t)((lrow * SLD + lcol) * 2);
        st.lcol  = lcol;
        st.szA   = (gr < M) ? 16 : 0;
    }

    float d[2][8][4];
    #pragma unroll
    for (int i = 0; i < 2; i++)
        #pragma unroll
        for (int j = 0; j < 8; j++)
            #pragma unroll
            for (int q = 0; q < 4; q++) d[i][j][q] = 0.f;

    const int nsl = K >> 5;
    GEMM_MAINLOOP(nsl);

    // epilogue
    #pragma unroll
    for (int fn = 0; fn < 8; fn++) {
        int ncol = wn * 64 + fn * 8 + 2 * tg;
        float2 bb = *(const float2*)&bias[ncol];
        int col = coff + ncol;
        #pragma unroll
        for (int fm = 0; fm < 2; fm++) {
            int r0 = bm + wm * 32 + fm * 16 + g;
            float v0 = d[fm][fn][0] + bb.x;
            float v1 = d[fm][fn][1] + bb.y;
            float v2 = d[fm][fn][2] + bb.x;
            float v3 = d[fm][fn][3] + bb.y;
            if (ACT == 1) {
                v0 = fmaxf(v0, 0.f); v1 = fmaxf(v1, 0.f);
                v2 = fmaxf(v2, 0.f); v3 = fmaxf(v3, 0.f);
            }
            if (r0 < M) {
                if (WF32) *(float2*)&Cf[(long)r0 * ldc + col] = make_float2(v0, v1);
                if (WSPLIT) {
                    uint32_t lo, hi = packsplit(v0, v1, lo);
                    *(uint32_t*)&Chi[(long)r0 * ldc + col] = hi;
                    *(uint32_t*)&Clo[(long)r0 * ldc + col] = lo;
                }
            }
            if (r0 + 8 < M) {
                if (WF32) *(float2*)&Cf[(long)(r0 + 8) * ldc + col] = make_float2(v2, v3);
                if (WSPLIT) {
                    uint32_t lo, hi = packsplit(v2, v3, lo);
                    *(uint32_t*)&Chi[(long)(r0 + 8) * ldc + col] = hi;
                    *(uint32_t*)&Clo[(long)(r0 + 8) * ldc + col] = lo;
                }
            }
        }
    }
}

// attention GEMM: tanh(z@W1+b1)·w2 reduced into g_wsum[r]; A = split z, M = RR*relN
__global__ __launch_bounds__(256, 2)
void tc_gemm_attn(const __nv_bfloat16* __restrict__ Ahi_, const __nv_bfloat16* __restrict__ Alo_,
                  const __nv_bfloat16* __restrict__ Bhi_, const __nv_bfloat16* __restrict__ Blo_,
                  const float* __restrict__ bias, const float* __restrict__ w2, int relN)
{
    extern __shared__ __nv_bfloat16 smd[];
    __shared__ float red[RR];
    const int M = RR * relN;
    const int K = HID;

    const int bm   = blockIdx.x * 128;
    const int tid  = threadIdx.x;
    const int lane = tid & 31;
    const int w    = tid >> 5;
    const int wm   = w & 3;
    const int wn   = w >> 2;
    const int g    = lane >> 2;
    const int tg   = lane & 3;
    const int lm_r = lane & 15;
    const int lm_c = (lane >> 4) << 3;
    const int lrow = tid >> 1;
    const int lcol = (tid & 1) * 16;

    if (tid < RR) red[tid] = 0.f;

    StageCtx st;
    {
        int gr = bm + lrow;
        int cr = (gr < M) ? gr : (M - 1);
        st.ahi = Ahi_ + (long)cr * K;
        st.alo = Alo_ + (long)cr * K;
        st.bhi = Bhi_ + (long)lrow * K;
        st.blo = Blo_ + (long)lrow * K;
        st.sbase = smem_u32(smd);
        st.soff  = (uint32_t)((lrow * SLD + lcol) * 2);
        st.lcol  = lcol;
        st.szA   = (gr < M) ? 16 : 0;
    }

    float d[2][8][4];
    #pragma unroll
    for (int i = 0; i < 2; i++)
        #pragma unroll
        for (int j = 0; j < 8; j++)
            #pragma unroll
            for (int q = 0; q < 4; q++) d[i][j][q] = 0.f;

    const int nsl = K >> 5;   // 4
    GEMM_MAINLOOP(nsl);

    float part[RR] = {0.f, 0.f, 0.f};
    #pragma unroll
    for (int fn = 0; fn < 8; fn++) {
        int ncol = wn * 64 + fn * 8 + 2 * tg;
        float2 bb = *(const float2*)&bias[ncol];
        float2 ww = *(const float2*)&w2[ncol];
        #pragma unroll
        for (int fm = 0; fm < 2; fm++) {
            int r0 = bm + wm * 32 + fm * 16 + g;
            int r1 = r0 + 8;
            if (r0 < M) {
                float s0 = tanhf(d[fm][fn][0] + bb.x) * ww.x
                         + tanhf(d[fm][fn][1] + bb.y) * ww.y;
                int rel = r0 / relN;
                part[0] += (rel == 0) ? s0 : 0.f;
                part[1] += (rel == 1) ? s0 : 0.f;
                part[2] += (rel == 2) ? s0 : 0.f;
            }
            if (r1 < M) {
                float s1 = tanhf(d[fm][fn][2] + bb.x) * ww.x
                         + tanhf(d[fm][fn][3] + bb.y) * ww.y;
                int rel = r1 / relN;
                part[0] += (rel == 0) ? s1 : 0.f;
                part[1] += (rel == 1) ? s1 : 0.f;
                part[2] += (rel == 2) ? s1 : 0.f;
            }
        }
    }
    #pragma unroll
    for (int r = 0; r < RR; r++) {
        float v = part[r];
        for (int off = 16; off > 0; off >>= 1) v += __shfl_down_sync(0xffffffffu, v, off);
        if (lane == 0 && v != 0.f) atomicAdd(&red[r], v);
    }
    __syncthreads();
    if (tid < RR) atomicAdd(&g_wsum[tid], red[tid]);
}

// ---------------- gather tss/rs into split feat cols [128,256) ----------------
__global__ void gather_embed(const float* __restrict__ tss, const float* __restrict__ rs,
                             const int* __restrict__ nid, __nv_bfloat16* __restrict__ fhi,
                             __nv_bfloat16* __restrict__ flo, int n)
{
    int gw   = (blockIdx.x * blockDim.x + threadIdx.x) >> 5;
    int lane = threadIdx.x & 31;
    if (gw >= n) return;
    int id = nid[gw];
    float4 v = (lane < 16) ? ((const float4*)(tss + (long)id * 64))[lane]
                           : ((const float4*)(rs  + (long)id * 64))[lane - 16];
    int col = 128 + lane * 4;
    uint32_t l0, l1;
    uint32_t h0 = packsplit(v.x, v.y, l0);
    uint32_t h1 = packsplit(v.z, v.w, l1);
    *(uint2*)&fhi[(long)gw * FEAT + col] = make_uint2(h0, h1);
    *(uint2*)&flo[(long)gw * FEAT + col] = make_uint2(l0, l1);
}

// ---------------- CSR build ----------------
__global__ void hist_kernel(const int* __restrict__ dst, int total, int E, int ndst)
{
    int i = blockIdx.x * blockDim.x + threadIdx.x;
    if (i >= total) return;
    int r = i / E;
    atomicAdd(&g_cnt[r * ndst + dst[i]], 1);
}

__global__ void scan_kernel(int n)
{
    __shared__ int ssum[1024];
    int tid   = threadIdx.x;
    int chunk = (n + 1023) >> 10;
    int base  = tid * chunk;
    int end   = min(base + chunk, n);

    int s = 0;
    for (int i = base; i < end; i++) s += g_cnt[i];
    ssum[tid] = s;
    __syncthreads();
    for (int off = 1; off < 1024; off <<= 1) {
        int v = (tid >= off) ? ssum[tid - off] : 0;
        __syncthreads();
        ssum[tid] += v;
        __syncthreads();
    }
    int p = ssum[tid] - s;
    for (int i = base; i < end; i++) { g_rowp[i] = p; g_cur[i] = p; p += g_cnt[i]; }
    if (tid == 1023) g_rowp[n] = ssum[1023];
    if (tid < RR) g_wsum[tid] = 0.f;
    __syncthreads();
    for (int i = tid; i < n; i += 1024) g_cnt[i] = 0;
}

__global__ void scatter_kernel(const int* __restrict__ src, const int* __restrict__ dst,
                               int total, int E, int ndst)
{
    int i = blockIdx.x * blockDim.x + threadIdx.x;
    if (i >= total) return;
    int r   = i / E;
    int pos = atomicAdd(&g_cur[r * ndst + dst[i]], 1);
    g_csr[pos] = src[i];
}

// ---------------- warp-per-dst aggregation (split in / split out) ----------------
__global__ void aggregate_kernel(const __nv_bfloat16* __restrict__ fhi,
                                 const __nv_bfloat16* __restrict__ flo,
                                 __nv_bfloat16* __restrict__ ahi,
                                 __nv_bfloat16* __restrict__ alo, int total)
{
    int gw   = (blockIdx.x * blockDim.x + threadIdx.x) >> 5;
    int lane = threadIdx.x & 31;
    if (gw >= total) return;

    int s = g_rowp[gw], e = g_rowp[gw + 1];
    float sm[8], mx[8];
    #pragma unroll
    for (int j = 0; j < 8; j++) { sm[j] = 0.f; mx[j] = -INFINITY; }

    for (int i = s; i < e; i++) {
        int srcn = g_csr[i];
        uint4 h = *(const uint4*)(fhi + (long)srcn * FEAT + lane * 8);
        uint4 l = *(const uint4*)(flo + (long)srcn * FEAT + lane * 8);
        float v[8];
        unpack8(h, l, v);
        #pragma unroll
        for (int j = 0; j < 8; j++) { sm[j] += v[j]; mx[j] = fmaxf(mx[j], v[j]); }
    }

    float deg = (float)(e - s);
    if (e == s) {
        #pragma unroll
        for (int j = 0; j < 8; j++) mx[j] = 0.f;
    }
    float inv = 1.f / fmaxf(deg, 1.f);
    float mean[8];
    #pragma unroll
    for (int j = 0; j < 8; j++) mean[j] = sm[j] * inv;

    long base = (long)gw * 768 + lane * 8;
    uint4 hi, lo;
    split8(mx, hi, lo);
    *(uint4*)&ahi[base] = hi;        *(uint4*)&alo[base] = lo;
    split8(mean, hi, lo);
    *(uint4*)&ahi[base + 256] = hi;  *(uint4*)&alo[base + 256] = lo;
    split8(sm, hi, lo);
    *(uint4*)&ahi[base + 512] = hi;  *(uint4*)&alo[base + 512] = lo;
}

// ---------------- combine: attention mix -> split feat1 + gathered embeds ----------------
__global__ void combine_kernel(const float* __restrict__ z, int N,
                               __nv_bfloat16* __restrict__ fhi, __nv_bfloat16* __restrict__ flo,
                               const float* __restrict__ tss, const float* __restrict__ rs,
                               const int* __restrict__ nid)
{
    int gw   = (blockIdx.x * blockDim.x + threadIdx.x) >> 5;
    int lane = threadIdx.x & 31;
    if (gw >= N) return;

    float w0 = g_wsum[0] / (float)N;
    float w1 = g_wsum[1] / (float)N;
    float w2 = g_wsum[2] / (float)N;
    float m  = fmaxf(w0, fmaxf(w1, w2));
    float e0 = expf(w0 - m), e1 = expf(w1 - m), e2 = expf(w2 - m);
    float inv = 1.f / (e0 + e1 + e2);
    float b0 = e0 * inv, b1 = e1 * inv, b2 = e2 * inv;

    long stride = (long)N * HID;
    const float4* z0 = (const float4*)(z + (long)gw * HID);
    const float4* z1 = (const float4*)(z + stride + (long)gw * HID);
    const float4* z2 = (const float4*)(z + 2 * stride + (long)gw * HID);
    float4 v0 = z0[lane], v1 = z1[lane], v2 = z2[lane];
    float hx = fmaxf(b0 * v0.x + b1 * v1.x + b2 * v2.x, 0.f);
    float hy = fmaxf(b0 * v0.y + b1 * v1.y + b2 * v2.y, 0.f);
    float hz = fmaxf(b0 * v0.z + b1 * v1.z + b2 * v2.z, 0.f);
    float hw = fmaxf(b0 * v0.w + b1 * v1.w + b2 * v2.w, 0.f);

    uint32_t l0, l1;
    uint32_t h0 = packsplit(hx, hy, l0);
    uint32_t h1 = packsplit(hz, hw, l1);
    *(uint2*)&fhi[(long)gw * FEAT + lane * 4] = make_uint2(h0, h1);
    *(uint2*)&flo[(long)gw * FEAT + lane * 4] = make_uint2(l0, l1);

    int id = nid[gw];
    float4 t = (lane < 16) ? ((const float4*)(tss + (long)id * 64))[lane]
                           : ((const float4*)(rs  + (long)id * 64))[lane - 16];
    int col = 128 + lane * 4;
    h0 = packsplit(t.x, t.y, l0);
    h1 = packsplit(t.z, t.w, l1);
    *(uint2*)&fhi[(long)gw * FEAT + col] = make_uint2(h0, h1);
    *(uint2*)&flo[(long)gw * FEAT + col] = make_uint2(l0, l1);
}

// ---------------- fused layer-2 combine + prediction ----------------
__global__ void combine_pred_kernel(const float* __restrict__ z, int N,
                                    const float* __restrict__ pw, const float* __restrict__ pb,
                                    float* __restrict__ out)
{
    int gw   = (blockIdx.x * blockDim.x + threadIdx.x) >> 5;
    int lane = threadIdx.x & 31;
    if (gw >= N) return;

    float w0 = g_wsum[0] / (float)N;
    float w1 = g_wsum[1] / (float)N;
    float w2 = g_wsum[2] / (float)N;
    float m  = fmaxf(w0, fmaxf(w1, w2));
    float e0 = expf(w0 - m), e1 = expf(w1 - m), e2 = expf(w2 - m);
    float inv = 1.f / (e0 + e1 + e2);
    float b0 = e0 * inv, b1 = e1 * inv, b2 = e2 * inv;

    long stride = (long)N * HID;
    const float4* z0 = (const float4*)(z + (long)gw * HID);
    const float4* z1 = (const float4*)(z + stride + (long)gw * HID);
    const float4* z2 = (const float4*)(z + 2 * stride + (long)gw * HID);
    float4 v0 = z0[lane], v1 = z1[lane], v2 = z2[lane];
    float hx = b0 * v0.x + b1 * v1.x + b2 * v2.x;
    float hy = b0 * v0.y + b1 * v1.y + b2 * v2.y;
    float hz = b0 * v0.z + b1 * v1.z + b2 * v2.z;
    float hw = b0 * v0.w + b1 * v1.w + b2 * v2.w;

    float4 w = ((const float4*)pw)[lane];
    float s = hx * w.x + hy * w.y + hz * w.z + hw * w.w;
    for (int off = 16; off > 0; off >>= 1) s += __shfl_down_sync(0xffffffffu, s, off);
    if (lane == 0) out[gw] = 1.f / (1.f + expf(-(s + pb[0])));
}

// ---------------- host ----------------
extern "C" void kernel_launch(void* const* d_in, const int* in_sizes, int n_in,
                              void* d_out, int out_size)
{
    const float* x_user   = (const float*)d_in[0];
    const float* tss      = (const float*)d_in[1];
    const float* rs       = (const float*)d_in[2];
    const int*   src_nid0 = (const int*)  d_in[3];
    const int*   src_nid1 = (const int*)  d_in[4];
    const int*   e0_src   = (const int*)  d_in[5];
    const int*   e0_dst   = (const int*)  d_in[6];
    const int*   e1_src   = (const int*)  d_in[7];
    const int*   e1_dst   = (const int*)  d_in[8];
    const float* embed_w  = (const float*)d_in[9];
    const float* embed_b  = (const float*)d_in[10];
    const float* l1_fc1_w = (const float*)d_in[11];
    const float* l1_fc1_b = (const float*)d_in[12];
    const float* l1_fc2_w = (const float*)d_in[13];
    const float* l1_fc2_b = (const float*)d_in[14];
    const float* l1_fc3_w = (const float*)d_in[15];
    const float* l1_fc3_b = (const float*)d_in[16];
    const float* l2_fc1_w = (const float*)d_in[17];
    const float* l2_fc1_b = (const float*)d_in[18];
    const float* l2_fc2_w = (const float*)d_in[19];
    const float* l2_fc2_b = (const float*)d_in[20];
    const float* l2_fc3_w = (const float*)d_in[21];
    const float* l2_fc3_b = (const float*)d_in[22];
    const float* attn_w1  = (const float*)d_in[23];
    const float* attn_b1  = (const float*)d_in[24];
    const float* attn_w2  = (const float*)d_in[25];
    const float* pred_w   = (const float*)d_in[26];
    const float* pred_b   = (const float*)d_in[27];
    float* out = (float*)d_out;

    __nv_bfloat16 *xhi, *xlo, *f0hi, *f0lo, *agghi, *agglo, *schi, *sclo;
    __nv_bfloat16 *zhi, *zlo, *f1hi, *f1lo, *whi, *wlo;
    float* z;
    cudaGetSymbolAddress((void**)&xhi,   g_xhi);
    cudaGetSymbolAddress((void**)&xlo,   g_xlo);
    cudaGetSymbolAddress((void**)&f0hi,  g_f0hi);
    cudaGetSymbolAddress((void**)&f0lo,  g_f0lo);
    cudaGetSymbolAddress((void**)&agghi, g_agghi);
    cudaGetSymbolAddress((void**)&agglo, g_agglo);
    cudaGetSymbolAddress((void**)&schi,  g_schi);
    cudaGetSymbolAddress((void**)&sclo,  g_sclo);
    cudaGetSymbolAddress((void**)&zhi,   g_zhi);
    cudaGetSymbolAddress((void**)&zlo,   g_zlo);
    cudaGetSymbolAddress((void**)&f1hi,  g_f1hi);
    cudaGetSymbolAddress((void**)&f1lo,  g_f1lo);
    cudaGetSymbolAddress((void**)&whi,   g_whi);
    cudaGetSymbolAddress((void**)&wlo,   g_wlo);
    cudaGetSymbolAddress((void**)&z,     g_z);

    cudaFuncSetAttribute(tc_gemm<0,0,1>, cudaFuncAttributeMaxDynamicSharedMemorySize, GEMM_SMEM_BYTES);
    cudaFuncSetAttribute(tc_gemm<1,0,1>, cudaFuncAttributeMaxDynamicSharedMemorySize, GEMM_SMEM_BYTES);
    cudaFuncSetAttribute(tc_gemm<0,1,1>, cudaFuncAttributeMaxDynamicSharedMemorySize, GEMM_SMEM_BYTES);
    cudaFuncSetAttribute(tc_gemm_attn,   cudaFuncAttributeMaxDynamicSharedMemorySize, GEMM_SMEM_BYTES);

    // ---- weight + input splits ----
    WJobs jobs;
    {
        int n = 0;
        jobs.j[n++] = {embed_w, OFF_EMBED, 128, 0};
        for (int r = 0; r < RR; r++)
            jobs.j[n++] = {l1_fc1_w + (long)r*256*128, OFF_L1FC1 + (long)r*256*128, 256, 0};
        for (int r = 0; r < RR; r++)
            jobs.j[n++] = {l1_fc2_w + (long)r*768*128, OFF_L1FC2 + (long)r*768*128, 768, 0};
        for (int r = 0; r < RR; r++)
            jobs.j[n++] = {l1_fc3_w + (long)r*256*128, OFF_L1FC3 + (long)r*256*128, 256, 0};
        for (int r = 0; r < RR; r++)
            jobs.j[n++] = {l2_fc1_w + (long)r*256*128, OFF_L2FC1 + (long)r*256*128, 256, 0};
        for (int r = 0; r < RR; r++)
            jobs.j[n++] = {l2_fc2_w + (long)r*768*128, OFF_L2FC2 + (long)r*768*128, 768, 0};
        for (int r = 0; r < RR; r++)
            jobs.j[n++] = {l2_fc3_w + (long)r*256*128, OFF_L2FC3 + (long)r*256*128, 256, 0};
        jobs.j[n++] = {attn_w1, OFF_ATTN, 128, 0};
    }
    split_all<<<dim3(24, 4, 20), dim3(32, 8)>>>(jobs, whi, wlo);
    split_x<<<CDIV(NN0*32, 256), 256>>>(x_user, xhi, xlo, (long)NN0 * 32);

    // ---- embed + feat0 ----
    tc_gemm<0,0,1><<<dim3(CDIV(NN0,128),1,1),256,GEMM_SMEM_BYTES>>>(
        xhi, xlo, whi+OFF_EMBED, wlo+OFF_EMBED, embed_b,
        (float*)0, f0hi, f0lo, NN0, 128, FEAT, 0, 0,0,0,0);
    gather_embed<<<CDIV(NN0*32,256),256>>>(tss, rs, src_nid0, f0hi, f0lo, NN0);

    // ---- layer 1 CSR + aggregate ----
    hist_kernel<<<CDIV(RR*EE0,256),256>>>(e0_dst, RR*EE0, EE0, NN1);
    scan_kernel<<<1,1024>>>(RR*NN1);
    scatter_kernel<<<CDIV(RR*EE0,256),256>>>(e0_src, e0_dst, RR*EE0, EE0, NN1);
    aggregate_kernel<<<CDIV(RR*NN1*32,256),256>>>(f0hi, f0lo, agghi, agglo, RR*NN1);

    // ---- layer 1 GEMMs ----
    tc_gemm<1,0,1><<<dim3(CDIV(NN1,128),1,RR),256,GEMM_SMEM_BYTES>>>(
        agghi, agglo, whi+OFF_L1FC2, wlo+OFF_L1FC2, l1_fc2_b,
        (float*)0, schi, sclo, NN1, 768, FEAT, 0, (long)NN1*768, 768*128, 128, (long)NN1*FEAT);
    tc_gemm<1,0,1><<<dim3(CDIV(NN1,128),1,RR),256,GEMM_SMEM_BYTES>>>(
        f0hi, f0lo, whi+OFF_L1FC1, wlo+OFF_L1FC1, l1_fc1_b,
        (float*)0, schi, sclo, NN1, 256, FEAT, 128, 0, 256*128, 128, (long)NN1*FEAT);
    tc_gemm<0,1,1><<<dim3(CDIV(NN1,128),1,RR),256,GEMM_SMEM_BYTES>>>(
        schi, sclo, whi+OFF_L1FC3, wlo+OFF_L1FC3, l1_fc3_b,
        z, zhi, zlo, NN1, 256, HID, 0, (long)NN1*256, 256*128, 128, (long)NN1*128);

    // ---- attention 1 (fused reduce) -> feat1 ----
    tc_gemm_attn<<<dim3(CDIV(RR*NN1,128),1,1),256,GEMM_SMEM_BYTES>>>(
        zhi, zlo, whi+OFF_ATTN, wlo+OFF_ATTN, attn_b1, attn_w2, NN1);
    combine_kernel<<<CDIV(NN1*32,256),256>>>(z, NN1, f1hi, f1lo, tss, rs, src_nid1);

    // ---- layer 2 CSR + aggregate ----
    hist_kernel<<<CDIV(RR*EE1,256),256>>>(e1_dst, RR*EE1, EE1, NN2);
    scan_kernel<<<1,1024>>>(RR*NN2);
    scatter_kernel<<<CDIV(RR*EE1,256),256>>>(e1_src, e1_dst, RR*EE1, EE1, NN2);
    aggregate_kernel<<<CDIV(RR*NN2*32,256),256>>>(f1hi, f1lo, agghi, agglo, RR*NN2);

    // ---- layer 2 GEMMs ----
    tc_gemm<1,0,1><<<dim3(CDIV(NN2,128),1,RR),256,GEMM_SMEM_BYTES>>>(
        agghi, agglo, whi+OFF_L2FC2, wlo+OFF_L2FC2, l2_fc2_b,
        (float*)0, schi, sclo, NN2, 768, FEAT, 0, (long)NN2*768, 768*128, 128, (long)NN2*FEAT);
    tc_gemm<1,0,1><<<dim3(CDIV(NN2,128),1,RR),256,GEMM_SMEM_BYTES>>>(
        f1hi, f1lo, whi+OFF_L2FC1, wlo+OFF_L2FC1, l2_fc1_b,
        (float*)0, schi, sclo, NN2, 256, FEAT, 128, 0, 256*128, 128, (long)NN2*FEAT);
    tc_gemm<0,1,1><<<dim3(CDIV(NN2,128),1,RR),256,GEMM_SMEM_BYTES>>>(
        schi, sclo, whi+OFF_L2FC3, wlo+OFF_L2FC3, l2_fc3_b,
        z, zhi, zlo, NN2, 256, HID, 0, (long)NN2*256, 256*128, 128, (long)NN2*128);

    // ---- attention 2 + fused combine/pred ----
    tc_gemm_attn<<<dim3(CDIV(RR*NN2,128),1,1),256,GEMM_SMEM_BYTES>>>(
        zhi, zlo, whi+OFF_ATTN, wlo+OFF_ATTN, attn_b1, attn_w2, NN2);
    combine_pred_kernel<<<CDIV(NN2*32,256),256>>>(z, NN2, pred_w, pred_b, out);
}

// round 17
// speedup vs baseline: 1.0883x; 1.0222x over previous
#include <cuda_runtime.h>
#include <cuda_bf16.h>
#include <math.h>
#include <stdint.h>

// ---------------- problem constants ----------------
#define NN0 100000
#define NN1 20000
#define NN2 4000
#define RR 3
#define EE0 160000
#define EE1 64000
#define HID 128
#define FEAT 256
#define CDIV(a,b) (((a)+(b)-1)/(b))

// ---------------- device scratch ----------------
__device__ __align__(16) float g_feat0[(size_t)NN0 * FEAT];
__device__ __align__(16) float g_agg[(size_t)RR * NN1 * 768];
__device__ __align__(16) float g_scratch[(size_t)RR * NN1 * FEAT];
__device__ __align__(16) float g_z[(size_t)RR * NN1 * HID];
__device__ __align__(16) float g_feat1[(size_t)NN1 * FEAT];
__device__ float g_wsum[RR];
__device__ int   g_cnt[RR * NN1];
__device__ int   g_cur[RR * NN1];
__device__ int   g_rowp[RR * NN1 + 1];
__device__ int   g_csr[RR * EE0];

// split-bf16 weights, transposed to [n=128][K]
#define W_TOTAL 1015808
__device__ __align__(16) __nv_bfloat16 g_whi[W_TOTAL];
__device__ __align__(16) __nv_bfloat16 g_wlo[W_TOTAL];

#define OFF_EMBED  0
#define OFF_L1FC1  16384
#define OFF_L1FC2  114688
#define OFF_L1FC3  409600
#define OFF_L2FC1  507904
#define OFF_L2FC2  606208
#define OFF_L2FC3  901120
#define OFF_ATTN   999424

// ---------------- helpers ----------------
__device__ __forceinline__ float4 f4add(float4 a, float4 b){
    return make_float4(a.x+b.x, a.y+b.y, a.z+b.z, a.w+b.w);
}
__device__ __forceinline__ float4 f4max(float4 a, float4 b){
    return make_float4(fmaxf(a.x,b.x), fmaxf(a.y,b.y), fmaxf(a.z,b.z), fmaxf(a.w,b.w));
}
__device__ __forceinline__ float4 f4scale(float4 a, float s){
    return make_float4(a.x*s, a.y*s, a.z*s, a.w*s);
}
__device__ __forceinline__ float tanh_fast(float x){
    float t;
    asm("tanh.approx.f32 %0, %1;" : "=f"(t) : "f"(x));
    return t;
}

#define MMA_BF16(D, A, B0, B1) \
  asm volatile("mma.sync.aligned.m16n8k16.row.col.f32.bf16.bf16.f32 " \
    "{%0,%1,%2,%3}, {%4,%5,%6,%7}, {%8,%9}, {%0,%1,%2,%3};\n" \
    : "+f"((D)[0]), "+f"((D)[1]), "+f"((D)[2]), "+f"((D)[3]) \
    : "r"((A)[0]), "r"((A)[1]), "r"((A)[2]), "r"((A)[3]), "r"(B0), "r"(B1))

#define LDSM_X4(R0,R1,R2,R3, ADDR) \
  asm volatile("ldmatrix.sync.aligned.m8n8.x4.shared.b16 {%0,%1,%2,%3},[%4];" \
    : "=r"(R0), "=r"(R1), "=r"(R2), "=r"(R3) : "r"(ADDR))

__device__ __forceinline__ uint32_t smem_u32(const void* p){
    return (uint32_t)__cvta_generic_to_shared(p);
}

// ---------------- fused weight transpose+split ----------------
struct WJob { const float* src; long doff; int K; int pad; };
struct WJobs { WJob j[20]; };

__global__ void split_all(WJobs jobs, __nv_bfloat16* __restrict__ Whi,
                          __nv_bfloat16* __restrict__ Wlo)
{
    WJob jb = jobs.j[blockIdx.z];
    int K = jb.K;
    int k0 = blockIdx.x * 32;
    if (k0 >= K) return;
    int n0 = blockIdx.y * 32;
    const float* W = jb.src;
    __nv_bfloat16* whi = Whi + jb.doff;
    __nv_bfloat16* wlo = Wlo + jb.doff;

    __shared__ float sm[32][33];
    int tx = threadIdx.x, ty = threadIdx.y;
    #pragma unroll
    for (int i = 0; i < 4; i++)
        sm[ty + i * 8][tx] = W[(long)(k0 + ty + i * 8) * 128 + n0 + tx];
    __syncthreads();
    #pragma unroll
    for (int i = 0; i < 4; i++) {
        float x = sm[tx][ty + i * 8];
        __nv_bfloat16 h = __float2bfloat16(x);
        float r = x - __bfloat162float(h);
        int n = n0 + ty + i * 8;
        whi[(long)n * K + k0 + tx] = h;
        wlo[(long)n * K + k0 + tx] = __float2bfloat16(r);
    }
}

// ================= tensor-core GEMM (R3 mainloop — proven fastest) =================
// C[M,128] = act(A[M,K] @ W[K,128] + bias); W pre-split [128][K].

#define TCG_DECL() \
    __shared__ __align__(16) __nv_bfloat16 sAhi[128][40]; \
    __shared__ __align__(16) __nv_bfloat16 sAlo[128][40]; \
    __shared__ __align__(16) __nv_bfloat16 sBhi[128][40]; \
    __shared__ __align__(16) __nv_bfloat16 sBlo[128][40]; \
    const int bm   = blockIdx.x * 128; \
    const int tid  = threadIdx.x; \
    const int lane = tid & 31; \
    const int w    = tid >> 5; \
    const int wm   = w & 3; \
    const int wn   = w >> 2; \
    const int g    = lane >> 2; \
    const int tg   = lane & 3; \
    const int lm_r = lane & 15; \
    const int lm_c = (lane >> 4) << 3; \
    const int lrow = tid >> 1; \
    const int lcol = (tid & 1) * 16; \
    float d[2][8][4]; \
    _Pragma("unroll") \
    for (int i = 0; i < 2; i++) \
        _Pragma("unroll") \
        for (int j = 0; j < 8; j++) \
            _Pragma("unroll") \
            for (int q = 0; q < 4; q++) d[i][j][q] = 0.f;

#define TCG_MAINLOOP(A_, Bhi_, Blo_, M_, K_) \
    for (int k0 = 0; k0 < (K_); k0 += 32) { \
        { \
            int gr = bm + lrow; \
            float4 v[4]; \
            if (gr < (M_)) { \
                const float4* p = (const float4*)((A_) + (long)gr * (K_) + k0 + lcol); \
                v[0] = p[0]; v[1] = p[1]; v[2] = p[2]; v[3] = p[3]; \
            } else { \
                v[0] = v[1] = v[2] = v[3] = make_float4(0.f, 0.f, 0.f, 0.f); \
            } \
            uint32_t hi[8], lo[8]; \
            _Pragma("unroll") \
            for (int i = 0; i < 4; i++) { \
                float x0 = v[i].x, x1 = v[i].y, x2 = v[i].z, x3 = v[i].w; \
                __nv_bfloat162 h01 = __floats2bfloat162_rn(x0, x1); \
                __nv_bfloat162 h23 = __floats2bfloat162_rn(x2, x3); \
                __nv_bfloat162 l01 = __floats2bfloat162_rn(x0 - __low2float(h01), \
                                                           x1 - __high2float(h01)); \
                __nv_bfloat162 l23 = __floats2bfloat162_rn(x2 - __low2float(h23), \
                                                           x3 - __high2float(h23)); \
                hi[2*i]   = *(uint32_t*)&h01;  hi[2*i+1] = *(uint32_t*)&h23; \
                lo[2*i]   = *(uint32_t*)&l01;  lo[2*i+1] = *(uint32_t*)&l23; \
            } \
            *(uint4*)&sAhi[lrow][lcol]     = make_uint4(hi[0], hi[1], hi[2], hi[3]); \
            *(uint4*)&sAhi[lrow][lcol + 8] = make_uint4(hi[4], hi[5], hi[6], hi[7]); \
            *(uint4*)&sAlo[lrow][lcol]     = make_uint4(lo[0], lo[1], lo[2], lo[3]); \
            *(uint4*)&sAlo[lrow][lcol + 8] = make_uint4(lo[4], lo[5], lo[6], lo[7]); \
        } \
        { \
            const uint4* ph = (const uint4*)((Bhi_) + (long)lrow * (K_) + k0 + lcol); \
            const uint4* pl = (const uint4*)((Blo_) + (long)lrow * (K_) + k0 + lcol); \
            uint4 h0 = ph[0], h1 = ph[1]; \
            uint4 l0 = pl[0], l1 = pl[1]; \
            *(uint4*)&sBhi[lrow][lcol]     = h0; \
            *(uint4*)&sBhi[lrow][lcol + 8] = h1; \
            *(uint4*)&sBlo[lrow][lcol]     = l0; \
            *(uint4*)&sBlo[lrow][lcol + 8] = l1; \
        } \
        __syncthreads(); \
        _Pragma("unroll") \
        for (int ks = 0; ks < 32; ks += 16) { \
            const int cc = ks + lm_c; \
            uint32_t ah[2][4], al[2][4]; \
            _Pragma("unroll") \
            for (int fm = 0; fm < 2; fm++) { \
                int r = wm * 32 + fm * 16 + lm_r; \
                LDSM_X4(ah[fm][0], ah[fm][1], ah[fm][2], ah[fm][3], \
                        smem_u32(&sAhi[r][cc])); \
                LDSM_X4(al[fm][0], al[fm][1], al[fm][2], al[fm][3], \
                        smem_u32(&sAlo[r][cc])); \
            } \
            _Pragma("unroll") \
            for (int t = 0; t < 4; t++) { \
                int nb = wn * 64 + t * 16 + lm_r; \
                uint32_t bh0, bh1, bh2, bh3, bl0, bl1, bl2, bl3; \
                LDSM_X4(bh0, bh1, bh2, bh3, smem_u32(&sBhi[nb][cc])); \
                LDSM_X4(bl0, bl1, bl2, bl3, smem_u32(&sBlo[nb][cc])); \
                _Pragma("unroll") \
                for (int fm = 0; fm < 2; fm++) { \
                    MMA_BF16(d[fm][2*t],   ah[fm], bh0, bh2); \
                    MMA_BF16(d[fm][2*t],   ah[fm], bl0, bl2); \
                    MMA_BF16(d[fm][2*t],   al[fm], bh0, bh2); \
                    MMA_BF16(d[fm][2*t+1], ah[fm], bh1, bh3); \
                    MMA_BF16(d[fm][2*t+1], ah[fm], bl1, bl3); \
                    MMA_BF16(d[fm][2*t+1], al[fm], bh1, bh3); \
                } \
            } \
        } \
        __syncthreads(); \
    }

#define TCG_EPILOGUE(C_, M_, LDC_, COFF_, BIAS_, ACT_) \
    _Pragma("unroll") \
    for (int fn = 0; fn < 8; fn++) { \
        int ncol = wn * 64 + fn * 8 + 2 * tg; \
        float2 bb = *(const float2*)&(BIAS_)[ncol]; \
        int col = (COFF_) + ncol; \
        _Pragma("unroll") \
        for (int fm = 0; fm < 2; fm++) { \
            int r0 = bm + wm * 32 + fm * 16 + g; \
            float v0 = d[fm][fn][0] + bb.x; \
            float v1 = d[fm][fn][1] + bb.y; \
            float v2 = d[fm][fn][2] + bb.x; \
            float v3 = d[fm][fn][3] + bb.y; \
            if (ACT_) { \
                v0 = fmaxf(v0, 0.f); v1 = fmaxf(v1, 0.f); \
                v2 = fmaxf(v2, 0.f); v3 = fmaxf(v3, 0.f); \
            } \
            if (r0 < (M_))     *(float2*)&(C_)[(long)r0 * (LDC_) + col]       = make_float2(v0, v1); \
            if (r0 + 8 < (M_)) *(float2*)&(C_)[(long)(r0 + 8) * (LDC_) + col] = make_float2(v2, v3); \
        } \
    }

// generic GEMM, batched over blockIdx.z
template<int ACT>
__global__ __launch_bounds__(256, 2)
void tc_gemm(const float* __restrict__ A, const __nv_bfloat16* __restrict__ Bhi,
             const __nv_bfloat16* __restrict__ Blo, const float* __restrict__ bias,
             float* __restrict__ C, int M, int K, int ldc, int coff,
             long sA, long sW, long sBias, long sC)
{
    A    += (long)blockIdx.z * sA;
    Bhi  += (long)blockIdx.z * sW;
    Blo  += (long)blockIdx.z * sW;
    bias += (long)blockIdx.z * sBias;
    C    += (long)blockIdx.z * sC;

    TCG_DECL();
    TCG_MAINLOOP(A, Bhi, Blo, M, K);
    TCG_EPILOGUE(C, M, ldc, coff, bias, ACT);
}

// embed GEMM with fused tss/rs gather into cols [128,256)
__global__ __launch_bounds__(256, 2)
void tc_gemm_embed(const float* __restrict__ A, const __nv_bfloat16* __restrict__ Bhi,
                   const __nv_bfloat16* __restrict__ Blo, const float* __restrict__ bias,
                   float* __restrict__ C, int M, int K,
                   const float* __restrict__ tss, const float* __restrict__ rs,
                   const int* __restrict__ nid)
{
    TCG_DECL();
    TCG_MAINLOOP(A, Bhi, Blo, M, K);
    TCG_EPILOGUE(C, M, FEAT, 0, bias, 0);

    // fused gather: warp per row, 16 rows per warp
    #pragma unroll
    for (int i = 0; i < 16; i++) {
        int row = bm + w * 16 + i;
        if (row < M) {
            int id = nid[row];
            float4* orow = (float4*)(C + (long)row * FEAT);
            if (lane < 16) orow[32 + lane] = ((const float4*)(tss + (long)id * 64))[lane];
            else           orow[48 + (lane - 16)] = ((const float4*)(rs + (long)id * 64))[lane - 16];
        }
    }
}

// attention GEMM: sum_cols tanh(z@W1+b1)*w2 accumulated into g_wsum[rel]
__global__ __launch_bounds__(256, 2)
void tc_gemm_attn(const float* __restrict__ A, const __nv_bfloat16* __restrict__ Bhi,
                  const __nv_bfloat16* __restrict__ Blo, const float* __restrict__ bias,
                  const float* __restrict__ w2, int relN)
{
    __shared__ __align__(16) float red[4];
    const int M = RR * relN;
    const int K = HID;

    TCG_DECL();
    if (tid < RR) red[tid] = 0.f;
    TCG_MAINLOOP(A, Bhi, Blo, M, K);

    float part[RR] = {0.f, 0.f, 0.f};
    #pragma unroll
    for (int fn = 0; fn < 8; fn++) {
        int ncol = wn * 64 + fn * 8 + 2 * tg;
        float2 bb = *(const float2*)&bias[ncol];
        float2 ww = *(const float2*)&w2[ncol];
        #pragma unroll
        for (int fm = 0; fm < 2; fm++) {
            int r0 = bm + wm * 32 + fm * 16 + g;
            int r1 = r0 + 8;
            if (r0 < M) {
                float s0 = tanh_fast(d[fm][fn][0] + bb.x) * ww.x
                         + tanh_fast(d[fm][fn][1] + bb.y) * ww.y;
                int rel = r0 / relN;
                part[0] += (rel == 0) ? s0 : 0.f;
                part[1] += (rel == 1) ? s0 : 0.f;
                part[2] += (rel == 2) ? s0 : 0.f;
            }
            if (r1 < M) {
                float s1 = tanh_fast(d[fm][fn][2] + bb.x) * ww.x
                         + tanh_fast(d[fm][fn][3] + bb.y) * ww.y;
                int rel = r1 / relN;
                part[0] += (rel == 0) ? s1 : 0.f;
                part[1] += (rel == 1) ? s1 : 0.f;
                part[2] += (rel == 2) ? s1 : 0.f;
            }
        }
    }
    #pragma unroll
    for (int r = 0; r < RR; r++) {
        float v = part[r];
        for (int off = 16; off > 0; off >>= 1) v += __shfl_down_sync(0xffffffffu, v, off);
        if (lane == 0 && v != 0.f) atomicAdd(&red[r], v);
    }
    __syncthreads();
    if (tid < RR) atomicAdd(&g_wsum[tid], red[tid]);
}

// ---------------- CSR build ----------------
__global__ void hist_kernel(const int* __restrict__ dst, int total, int E, int ndst)
{
    int i = blockIdx.x * blockDim.x + threadIdx.x;
    if (i >= total) return;
    int r = i / E;
    atomicAdd(&g_cnt[r * ndst + dst[i]], 1);
}

// exclusive scan of g_cnt -> g_rowp + cursor copy; re-zero g_cnt; zero g_wsum
__global__ void scan_kernel(int n)
{
    __shared__ int ssum[1024];
    int tid   = threadIdx.x;
    int chunk = (n + 1023) >> 10;
    int base  = tid * chunk;
    int end   = min(base + chunk, n);

    int s = 0;
    for (int i = base; i < end; i++) s += g_cnt[i];
    ssum[tid] = s;
    __syncthreads();
    for (int off = 1; off < 1024; off <<= 1) {
        int v = (tid >= off) ? ssum[tid - off] : 0;
        __syncthreads();
        ssum[tid] += v;
        __syncthreads();
    }
    int p = ssum[tid] - s;
    for (int i = base; i < end; i++) { g_rowp[i] = p; g_cur[i] = p; p += g_cnt[i]; }
    if (tid == 1023) g_rowp[n] = ssum[1023];
    if (tid < RR) g_wsum[tid] = 0.f;
    __syncthreads();
    for (int i = tid; i < n; i += 1024) g_cnt[i] = 0;
}

__global__ void scatter_kernel(const int* __restrict__ src, const int* __restrict__ dst,
                               int total, int E, int ndst)
{
    int i = blockIdx.x * blockDim.x + threadIdx.x;
    if (i >= total) return;
    int r   = i / E;
    int pos = atomicAdd(&g_cur[r * ndst + dst[i]], 1);
    g_csr[pos] = src[i];
}

// ---------------- warp-per-dst aggregation ----------------
__global__ void aggregate_kernel(const float* __restrict__ feat, float* __restrict__ agg, int total)
{
    int gw   = (blockIdx.x * blockDim.x + threadIdx.x) >> 5;
    int lane = threadIdx.x & 31;
    if (gw >= total) return;

    int s = g_rowp[gw], e = g_rowp[gw + 1];
    float4 sa = make_float4(0.f, 0.f, 0.f, 0.f), sb = sa;
    float4 ma = make_float4(-INFINITY, -INFINITY, -INFINITY, -INFINITY), mb = ma;

    int i = s;
    for (; i + 1 < e; i += 2) {
        int s0 = g_csr[i], s1 = g_csr[i + 1];
        const float4* p0 = (const float4*)(feat + (long)s0 * FEAT);
        const float4* p1 = (const float4*)(feat + (long)s1 * FEAT);
        float4 va0 = p0[lane], vb0 = p0[lane + 32];
        float4 va1 = p1[lane], vb1 = p1[lane + 32];
        sa = f4add(sa, f4add(va0, va1));  sb = f4add(sb, f4add(vb0, vb1));
        ma = f4max(ma, f4max(va0, va1));  mb = f4max(mb, f4max(vb0, vb1));
    }
    if (i < e) {
        int s0 = g_csr[i];
        const float4* p0 = (const float4*)(feat + (long)s0 * FEAT);
        float4 va0 = p0[lane], vb0 = p0[lane + 32];
        sa = f4add(sa, va0);  sb = f4add(sb, vb0);
        ma = f4max(ma, va0);  mb = f4max(mb, vb0);
    }

    float deg = (float)(e - s);
    if (e == s) { ma = make_float4(0.f,0.f,0.f,0.f); mb = ma; }
    float inv = 1.f / fmaxf(deg, 1.f);

    float4* o = (float4*)(agg + (long)gw * 768);
    o[lane]       = ma;                 o[32 + lane]  = mb;
    o[64 + lane]  = f4scale(sa, inv);   o[96 + lane]  = f4scale(sb, inv);
    o[128 + lane] = sa;                 o[160 + lane] = sb;
}

// ---------------- combine (attention mix) -> feat1 + gathered embeds ----------------
__global__ void combine_kernel(const float* __restrict__ z, int N,
                               float* __restrict__ out, int ldo,
                               const float* __restrict__ tss, const float* __restrict__ rs,
                               const int* __restrict__ nid)
{
    int gw   = (blockIdx.x * blockDim.x + threadIdx.x) >> 5;
    int lane = threadIdx.x & 31;
    if (gw >= N) return;

    float w0 = g_wsum[0] / (float)N;
    float w1 = g_wsum[1] / (float)N;
    float w2 = g_wsum[2] / (float)N;
    float m  = fmaxf(w0, fmaxf(w1, w2));
    float e0 = expf(w0 - m), e1 = expf(w1 - m), e2 = expf(w2 - m);
    float inv = 1.f / (e0 + e1 + e2);
    float b0 = e0 * inv, b1 = e1 * inv, b2 = e2 * inv;

    long stride = (long)N * HID;
    const float4* z0 = (const float4*)(z + (long)gw * HID);
    const float4* z1 = (const float4*)(z + stride + (long)gw * HID);
    const float4* z2 = (const float4*)(z + 2 * stride + (long)gw * HID);
    float4 v0 = z0[lane], v1 = z1[lane], v2 = z2[lane];
    float4 h;
    h.x = fmaxf(b0 * v0.x + b1 * v1.x + b2 * v2.x, 0.f);
    h.y = fmaxf(b0 * v0.y + b1 * v1.y + b2 * v2.y, 0.f);
    h.z = fmaxf(b0 * v0.z + b1 * v1.z + b2 * v2.z, 0.f);
    h.w = fmaxf(b0 * v0.w + b1 * v1.w + b2 * v2.w, 0.f);

    float4* orow = (float4*)(out + (long)gw * ldo);
    orow[lane] = h;

    int id = nid[gw];
    if (lane < 16) orow[32 + lane] = ((const float4*)(tss + (long)id * 64))[lane];
    else           orow[48 + (lane - 16)] = ((const float4*)(rs + (long)id * 64))[lane - 16];
}

// ---------------- fused layer-2 combine + prediction ----------------
__global__ void combine_pred_kernel(const float* __restrict__ z, int N,
                                    const float* __restrict__ pw, const float* __restrict__ pb,
                                    float* __restrict__ out)
{
    int gw   = (blockIdx.x * blockDim.x + threadIdx.x) >> 5;
    int lane = threadIdx.x & 31;
    if (gw >= N) return;

    float w0 = g_wsum[0] / (float)N;
    float w1 = g_wsum[1] / (float)N;
    float w2 = g_wsum[2] / (float)N;
    float m  = fmaxf(w0, fmaxf(w1, w2));
    float e0 = expf(w0 - m), e1 = expf(w1 - m), e2 = expf(w2 - m);
    float inv = 1.f / (e0 + e1 + e2);
    float b0 = e0 * inv, b1 = e1 * inv, b2 = e2 * inv;

    long stride = (long)N * HID;
    const float4* z0 = (const float4*)(z + (long)gw * HID);
    const float4* z1 = (const float4*)(z + stride + (long)gw * HID);
    const float4* z2 = (const float4*)(z + 2 * stride + (long)gw * HID);
    float4 v0 = z0[lane], v1 = z1[lane], v2 = z2[lane];
    float hx = b0 * v0.x + b1 * v1.x + b2 * v2.x;
    float hy = b0 * v0.y + b1 * v1.y + b2 * v2.y;
    float hz = b0 * v0.z + b1 * v1.z + b2 * v2.z;
    float hw = b0 * v0.w + b1 * v1.w + b2 * v2.w;

    float4 w = ((const float4*)pw)[lane];
    float s = hx * w.x + hy * w.y + hz * w.z + hw * w.w;
    for (int off = 16; off > 0; off >>= 1) s += __shfl_down_sync(0xffffffffu, s, off);
    if (lane == 0) out[gw] = 1.f / (1.f + expf(-(s + pb[0])));
}

// ---------------- host ----------------
extern "C" void kernel_launch(void* const* d_in, const int* in_sizes, int n_in,
                              void* d_out, int out_size)
{
    const float* x_user   = (const float*)d_in[0];
    const float* tss      = (const float*)d_in[1];
    const float* rs       = (const float*)d_in[2];
    const int*   src_nid0 = (const int*)  d_in[3];
    const int*   src_nid1 = (const int*)  d_in[4];
    const int*   e0_src   = (const int*)  d_in[5];
    const int*   e0_dst   = (const int*)  d_in[6];
    const int*   e1_src   = (const int*)  d_in[7];
    const int*   e1_dst   = (const int*)  d_in[8];
    const float* embed_w  = (const float*)d_in[9];
    const float* embed_b  = (const float*)d_in[10];
    const float* l1_fc1_w = (const float*)d_in[11];
    const float* l1_fc1_b = (const float*)d_in[12];
    const float* l1_fc2_w = (const float*)d_in[13];
    const float* l1_fc2_b = (const float*)d_in[14];
    const float* l1_fc3_w = (const float*)d_in[15];
    const float* l1_fc3_b = (const float*)d_in[16];
    const float* l2_fc1_w = (const float*)d_in[17];
    const float* l2_fc1_b = (const float*)d_in[18];
    const float* l2_fc2_w = (const float*)d_in[19];
    const float* l2_fc2_b = (const float*)d_in[20];
    const float* l2_fc3_w = (const float*)d_in[21];
    const float* l2_fc3_b = (const float*)d_in[22];
    const float* attn_w1  = (const float*)d_in[23];
    const float* attn_b1  = (const float*)d_in[24];
    const float* attn_w2  = (const float*)d_in[25];
    const float* pred_w   = (const float*)d_in[26];
    const float* pred_b   = (const float*)d_in[27];
    float* out = (float*)d_out;

    float *feat0, *agg, *scratch, *z, *feat1;
    __nv_bfloat16 *whi, *wlo;
    cudaGetSymbolAddress((void**)&feat0,   g_feat0);
    cudaGetSymbolAddress((void**)&agg,     g_agg);
    cudaGetSymbolAddress((void**)&scratch, g_scratch);
    cudaGetSymbolAddress((void**)&z,       g_z);
    cudaGetSymbolAddress((void**)&feat1,   g_feat1);
    cudaGetSymbolAddress((void**)&whi,     g_whi);
    cudaGetSymbolAddress((void**)&wlo,     g_wlo);

    // ---- fused weight split ----
    WJobs jobs;
    {
        int n = 0;
        jobs.j[n++] = {embed_w, OFF_EMBED, 128, 0};
        for (int r = 0; r < RR; r++)
            jobs.j[n++] = {l1_fc1_w + (long)r*256*128, OFF_L1FC1 + (long)r*256*128, 256, 0};
        for (int r = 0; r < RR; r++)
            jobs.j[n++] = {l1_fc2_w + (long)r*768*128, OFF_L1FC2 + (long)r*768*128, 768, 0};
        for (int r = 0; r < RR; r++)
            jobs.j[n++] = {l1_fc3_w + (long)r*256*128, OFF_L1FC3 + (long)r*256*128, 256, 0};
        for (int r = 0; r < RR; r++)
            jobs.j[n++] = {l2_fc1_w + (long)r*256*128, OFF_L2FC1 + (long)r*256*128, 256, 0};
        for (int r = 0; r < RR; r++)
            jobs.j[n++] = {l2_fc2_w + (long)r*768*128, OFF_L2FC2 + (long)r*768*128, 768, 0};
        for (int r = 0; r < RR; r++)
            jobs.j[n++] = {l2_fc3_w + (long)r*256*128, OFF_L2FC3 + (long)r*256*128, 256, 0};
        jobs.j[n++] = {attn_w1, OFF_ATTN, 128, 0};
    }
    split_all<<<dim3(24, 4, 20), dim3(32, 8)>>>(jobs, whi, wlo);

    // ---- embed + fused gather -> feat0 ----
    tc_gemm_embed<<<dim3(CDIV(NN0,128),1,1),256>>>(
        x_user, whi+OFF_EMBED, wlo+OFF_EMBED, embed_b, feat0, NN0, 128,
        tss, rs, src_nid0);

    // ---- layer 1 CSR + aggregate ----
    hist_kernel<<<CDIV(RR*EE0,256),256>>>(e0_dst, RR*EE0, EE0, NN1);
    scan_kernel<<<1,1024>>>(RR*NN1);
    scatter_kernel<<<CDIV(RR*EE0,256),256>>>(e0_src, e0_dst, RR*EE0, EE0, NN1);
    aggregate_kernel<<<CDIV(RR*NN1*32,256),256>>>(feat0, agg, RR*NN1);

    // ---- layer 1 GEMMs ----
    tc_gemm<1><<<dim3(CDIV(NN1,128),1,RR),256>>>(agg, whi+OFF_L1FC2, wlo+OFF_L1FC2,
        l1_fc2_b, scratch, NN1, 768, FEAT, 0, (long)NN1*768, 768*128, 128, (long)NN1*FEAT);
    tc_gemm<1><<<dim3(CDIV(NN1,128),1,RR),256>>>(feat0, whi+OFF_L1FC1, wlo+OFF_L1FC1,
        l1_fc1_b, scratch, NN1, 256, FEAT, 128, 0, 256*128, 128, (long)NN1*FEAT);
    tc_gemm<0><<<dim3(CDIV(NN1,128),1,RR),256>>>(scratch, whi+OFF_L1FC3, wlo+OFF_L1FC3,
        l1_fc3_b, z, NN1, 256, HID, 0, (long)NN1*FEAT, 256*128, 128, (long)NN1*HID);

    // ---- attention 1 (fused reduce) -> feat1 ----
    tc_gemm_attn<<<dim3(CDIV(RR*NN1,128),1,1),256>>>(z, whi+OFF_ATTN, wlo+OFF_ATTN,
        attn_b1, attn_w2, NN1);
    combine_kernel<<<CDIV(NN1*32,256),256>>>(z, NN1, feat1, FEAT, tss, rs, src_nid1);

    // ---- layer 2 CSR + aggregate ----
    hist_kernel<<<CDIV(RR*EE1,256),256>>>(e1_dst, RR*EE1, EE1, NN2);
    scan_kernel<<<1,1024>>>(RR*NN2);
    scatter_kernel<<<CDIV(RR*EE1,256),256>>>(e1_src, e1_dst, RR*EE1, EE1, NN2);
    aggregate_kernel<<<CDIV(RR*NN2*32,256),256>>>(feat1, agg, RR*NN2);

    // ---- layer 2 GEMMs ----
    tc_gemm<1><<<dim3(CDIV(NN2,128),1,RR),256>>>(agg, whi+OFF_L2FC2, wlo+OFF_L2FC2,
        l2_fc2_b, scratch, NN2, 768, FEAT, 0, (long)NN2*768, 768*128, 128, (long)NN2*FEAT);
    tc_gemm<1><<<dim3(CDIV(NN2,128),1,RR),256>>>(feat1, whi+OFF_L2FC1, wlo+OFF_L2FC1,
        l2_fc1_b, scratch, NN2, 256, FEAT, 128, 0, 256*128, 128, (long)NN2*FEAT);
    tc_gemm<0><<<dim3(CDIV(NN2,128),1,RR),256>>>(scratch, whi+OFF_L2FC3, wlo+OFF_L2FC3,
        l2_fc3_b, z, NN2, 256, HID, 0, (long)NN2*FEAT, 256*128, 128, (long)NN2*HID);

    // ---- attention 2 + fused combine/pred ----
    tc_gemm_attn<<<dim3(CDIV(RR*NN2,128),1,1),256>>>(z, whi+OFF_ATTN, wlo+OFF_ATTN,
        attn_b1, attn_w2, NN2);
    combine_pred_kernel<<<CDIV(NN2*32,256),256>>>(z, NN2, pred_w, pred_b, out);
}